// round 11
// baseline (speedup 1.0000x reference)
#include <cuda_runtime.h>
#include <cuda_fp16.h>
#include <math.h>
#include <stdint.h>

// ---------------------------------------------------------------------------
// CSTreeLSTM on GB300: single-term fp16 HMMA GEMMs (fp32 accumulate),
// fp16 cross-kernel intermediates, heterogeneous combo launches that co-run
// independent GEMMs (gates_d || FH_{d+1}) in one grid.
// Tree: 16-ary, depth 4, IN=HID=512. Levels 1,16,256,4096,65536
// (offsets 0,1,17,273,4369; total 69905).
// ---------------------------------------------------------------------------

#define IN_DIM 512
#define HID    512
#define NLEAF  65536
#define NTOT   69905

typedef __half hlf;

// ------------------------------ device scratch ------------------------------
__device__ __align__(128) float g_C [NTOT * HID];
__device__ __align__(128) float g_H [NTOT * HID];
__device__ __align__(128) hlf   g_FHh[NTOT * HID];
__device__ __align__(128) float g_G [4096 * 2048];

__device__ __align__(128) hlf g_Xh [NLEAF * IN_DIM];
__device__ __align__(128) hlf g_Ch [NTOT * HID];
__device__ __align__(128) hlf g_Hh [NLEAF * HID];
__device__ __align__(128) hlf g_XHh[4096 * 1024];

__device__ __align__(128) hlf g_Wnh[2048 * 1024];
__device__ __align__(128) hlf g_Wlh[1536 * 512];
__device__ __align__(128) hlf g_Wfhh[512 * 512];
__device__ float g_bleaf[1536];
__device__ float g_bnode[2048];

__device__ __forceinline__ float sigf(float x) { return 1.f / (1.f + expf(-x)); }

// ------------------------------ PTX helpers ---------------------------------
__device__ __forceinline__ uint32_t smem_u32(const void* p) {
    uint32_t a;
    asm("{ .reg .u64 t; cvta.to.shared.u64 t, %1; cvt.u32.u64 %0, t; }" : "=r"(a) : "l"(p));
    return a;
}

__device__ __forceinline__ void cp16(uint32_t dst, const void* src) {
    asm volatile("cp.async.cg.shared.global [%0], [%1], 16;" :: "r"(dst), "l"(src));
}
#define CP_COMMIT() asm volatile("cp.async.commit_group;" ::: "memory")

__device__ __forceinline__ void ldsm4(uint32_t* r, uint32_t addr) {
    asm volatile("ldmatrix.sync.aligned.m8n8.x4.shared.b16 {%0,%1,%2,%3}, [%4];"
                 : "=r"(r[0]), "=r"(r[1]), "=r"(r[2]), "=r"(r[3]) : "r"(addr));
}
__device__ __forceinline__ void mma16816(float* d, const uint32_t* a, const uint32_t* b) {
    asm volatile(
        "mma.sync.aligned.m16n8k16.row.col.f32.f16.f16.f32 "
        "{%0,%1,%2,%3}, {%4,%5,%6,%7}, {%8,%9}, {%0,%1,%2,%3};"
        : "+f"(d[0]), "+f"(d[1]), "+f"(d[2]), "+f"(d[3])
        : "r"(a[0]), "r"(a[1]), "r"(a[2]), "r"(a[3]), "r"(b[0]), "r"(b[1]));
}

__device__ __forceinline__ float4 h4_to_f4(uint2 u) {
    __half2 lo = *(__half2*)&u.x, hi = *(__half2*)&u.y;
    float2 a = __half22float2(lo), b = __half22float2(hi);
    return make_float4(a.x, a.y, b.x, b.y);
}

// ---------------------------------------------------------------------------
// GEMM bodies (device functions). Big: CTA 128x256, 512 thr, 16 warps.
// Small: CTA 64x64, active on first 128 threads (others idle thru syncs).
// ---------------------------------------------------------------------------
#define TPITCH 80
#define AT_B (128 * TPITCH)
#define BT_B (256 * TPITCH)
#define STAGE_B (AT_B + BT_B)
#define GSMEM (3 * STAGE_B + 128)

#define G64_T (64 * TPITCH)
#define G64_STAGE (2 * G64_T)

struct GemmJob {
    const hlf* A; const hlf* B; void* C; const float* bias;
    int M, N, K, half_out, path, gx, nblk;   // path: 0=big, 1=small
};

__device__ __forceinline__ void gemm_big_body(const GemmJob& J, int bx, int by,
                                              uint32_t sbase) {
    const int tid  = threadIdx.x;
    const int lane = tid & 31;
    const int wid  = tid >> 5;
    const int wm   = wid >> 2;
    const int wn   = wid & 3;
    const int bm   = by * 128;
    const int bn   = bx * 256;
    const int M = J.M, N = J.N, K = J.K;
    const int NC   = K >> 5;
    const hlf* __restrict__ Ah = J.A;
    const hlf* __restrict__ Bh = J.B;

    const int ag = lane >> 3, ai = lane & 7;
    const int a_row = ai + (ag & 1) * 8;
    const int a_kb  = (ag >> 1) * 16;
    const int b_row2 = (lane & 7) + ((lane >> 4) << 3);
    const int b_kb   = ((lane >> 3) & 1) * 16;

    float acc[2][8][4];
#pragma unroll
    for (int mt = 0; mt < 2; mt++)
#pragma unroll
        for (int nt = 0; nt < 8; nt++)
#pragma unroll
            for (int j = 0; j < 4; j++) acc[mt][nt][j] = 0.f;

    auto load_chunk = [&](int c, int s) {
        const uint32_t sb = sbase + s * STAGE_B;
        const int k0 = c << 5;
        {
            int row = tid >> 2, cb = tid & 3;
            int ar = bm + row; if (ar > M - 1) ar = M - 1;
            size_t aoff = (size_t)ar * K + k0 + cb * 8;
            cp16(sb + row * TPITCH + cb * 16, Ah + aoff);
        }
#pragma unroll
        for (int i = 0; i < 2; ++i) {
            int p = tid + i * 512;
            int row = p >> 2, cb = p & 3;
            size_t boff = (size_t)(bn + row) * K + k0 + cb * 8;
            cp16(sb + AT_B + row * TPITCH + cb * 16, Bh + boff);
        }
        CP_COMMIT();
    };

    load_chunk(0, 0);
    if (NC > 1) load_chunk(1, 1);

    for (int c = 0; c < NC; ++c) {
        if (c + 2 < NC) load_chunk(c + 2, (c + 2) % 3);

        if (c + 2 < NC)      asm volatile("cp.async.wait_group 2;" ::: "memory");
        else if (c + 1 < NC) asm volatile("cp.async.wait_group 1;" ::: "memory");
        else                 asm volatile("cp.async.wait_group 0;" ::: "memory");
        __syncthreads();

        const uint32_t sb  = sbase + (c % 3) * STAGE_B;
        const uint32_t tAh = sb, tBh = sb + AT_B;

#pragma unroll
        for (int ks = 0; ks < 2; ++ks) {
            const int kb = ks * 32;
            uint32_t ah[2][4], bh[8][2];
#pragma unroll
            for (int mt = 0; mt < 2; ++mt) {
                uint32_t ro = (wm * 32 + mt * 16 + a_row) * TPITCH + a_kb + kb;
                ldsm4(ah[mt], tAh + ro);
            }
#pragma unroll
            for (int nt2 = 0; nt2 < 8; nt2 += 2) {
                uint32_t ro = (wn * 64 + nt2 * 8 + b_row2) * TPITCH + b_kb + kb;
                ldsm4(&bh[nt2][0], tBh + ro);
            }
#pragma unroll
            for (int mt = 0; mt < 2; ++mt)
#pragma unroll
                for (int nt = 0; nt < 8; ++nt)
                    mma16816(acc[mt][nt], ah[mt], bh[nt]);
        }
        __syncthreads();
    }

    const int r0 = lane >> 2;
    const int q2 = (lane & 3) * 2;
#pragma unroll
    for (int mt = 0; mt < 2; ++mt) {
        int row = bm + wm * 32 + mt * 16 + r0;
#pragma unroll
        for (int nt = 0; nt < 8; ++nt) {
            int col = bn + wn * 64 + nt * 8 + q2;
            float bx_ = 0.f, by_ = 0.f;
            if (J.bias) { bx_ = J.bias[col]; by_ = J.bias[col + 1]; }
            float v00 = acc[mt][nt][0] + bx_, v01 = acc[mt][nt][1] + by_;
            float v10 = acc[mt][nt][2] + bx_, v11 = acc[mt][nt][3] + by_;
            if (J.half_out) {
                hlf* Ch = (hlf*)J.C;
                if (row < M) {
                    __half2 v; v.x = __float2half_rn(v00); v.y = __float2half_rn(v01);
                    *(__half2*)(Ch + (size_t)row * N + col) = v;
                }
                if (row + 8 < M) {
                    __half2 v; v.x = __float2half_rn(v10); v.y = __float2half_rn(v11);
                    *(__half2*)(Ch + (size_t)(row + 8) * N + col) = v;
                }
            } else {
                float* Cf = (float*)J.C;
                if (row < M)
                    *(float2*)(Cf + (size_t)row * N + col) = make_float2(v00, v01);
                if (row + 8 < M)
                    *(float2*)(Cf + (size_t)(row + 8) * N + col) = make_float2(v10, v11);
            }
        }
    }
}

__device__ __forceinline__ void gemm_small_body(const GemmJob& J, int bx, int by,
                                                uint32_t sbase) {
    const int tid  = threadIdx.x;
    const int lane = tid & 31;
    const int wid  = tid >> 5;
    const int wm   = wid >> 1;        // valid for wid<4
    const int wn   = wid & 1;
    const int bm   = by * 64;
    const int bn   = bx * 64;
    const int M = J.M, N = J.N, K = J.K;
    const int NC   = K >> 5;
    const hlf* __restrict__ Ah = J.A;
    const hlf* __restrict__ Bh = J.B;

    const int ag = lane >> 3, ai = lane & 7;
    const int a_row = ai + (ag & 1) * 8;
    const int a_kb  = (ag >> 1) * 16;
    const int b_row2 = (lane & 7) + ((lane >> 4) << 3);
    const int b_kb   = ((lane >> 3) & 1) * 16;

    float acc[2][4][4];
#pragma unroll
    for (int mt = 0; mt < 2; mt++)
#pragma unroll
        for (int nt = 0; nt < 4; nt++)
#pragma unroll
            for (int j = 0; j < 4; j++) acc[mt][nt][j] = 0.f;

    auto load_chunk = [&](int c, int s) {
        const uint32_t sb = sbase + s * G64_STAGE;
        const int k0 = c << 5;
        if (tid < 256) {
            int row = tid >> 2, cb = tid & 3;
            int ar = bm + row; if (ar > M - 1) ar = M - 1;
            size_t aoff = (size_t)ar * K + k0 + cb * 8;
            size_t boff = (size_t)(bn + row) * K + k0 + cb * 8;
            uint32_t so = row * TPITCH + cb * 16;
            cp16(sb + so,         Ah + aoff);
            cp16(sb + G64_T + so, Bh + boff);
        }
        CP_COMMIT();
    };

    load_chunk(0, 0);
    if (NC > 1) load_chunk(1, 1);

    for (int c = 0; c < NC; ++c) {
        if (c + 2 < NC) load_chunk(c + 2, (c + 2) % 3);

        if (c + 2 < NC)      asm volatile("cp.async.wait_group 2;" ::: "memory");
        else if (c + 1 < NC) asm volatile("cp.async.wait_group 1;" ::: "memory");
        else                 asm volatile("cp.async.wait_group 0;" ::: "memory");
        __syncthreads();

        if (wid < 4) {
            const uint32_t sb  = sbase + (c % 3) * G64_STAGE;
            const uint32_t tAh = sb, tBh = sb + G64_T;
#pragma unroll
            for (int ks = 0; ks < 2; ++ks) {
                const int kb = ks * 32;
                uint32_t ah[2][4], bh[4][2];
#pragma unroll
                for (int mt = 0; mt < 2; ++mt) {
                    uint32_t ro = (wm * 32 + mt * 16 + a_row) * TPITCH + a_kb + kb;
                    ldsm4(ah[mt], tAh + ro);
                }
#pragma unroll
                for (int nt2 = 0; nt2 < 4; nt2 += 2) {
                    uint32_t ro = (wn * 32 + nt2 * 8 + b_row2) * TPITCH + b_kb + kb;
                    ldsm4(&bh[nt2][0], tBh + ro);
                }
#pragma unroll
                for (int mt = 0; mt < 2; ++mt)
#pragma unroll
                    for (int nt = 0; nt < 4; ++nt)
                        mma16816(acc[mt][nt], ah[mt], bh[nt]);
            }
        }
        __syncthreads();
    }

    if (wid < 4) {
        const int r0 = lane >> 2;
        const int q2 = (lane & 3) * 2;
#pragma unroll
        for (int mt = 0; mt < 2; ++mt) {
            int row = bm + wm * 32 + mt * 16 + r0;
#pragma unroll
            for (int nt = 0; nt < 4; ++nt) {
                int col = bn + wn * 32 + nt * 8 + q2;
                float bx_ = 0.f, by_ = 0.f;
                if (J.bias) { bx_ = J.bias[col]; by_ = J.bias[col + 1]; }
                float v00 = acc[mt][nt][0] + bx_, v01 = acc[mt][nt][1] + by_;
                float v10 = acc[mt][nt][2] + bx_, v11 = acc[mt][nt][3] + by_;
                if (J.half_out) {
                    hlf* Ch = (hlf*)J.C;
                    if (row < M) {
                        __half2 v; v.x = __float2half_rn(v00); v.y = __float2half_rn(v01);
                        *(__half2*)(Ch + (size_t)row * N + col) = v;
                    }
                    if (row + 8 < M) {
                        __half2 v; v.x = __float2half_rn(v10); v.y = __float2half_rn(v11);
                        *(__half2*)(Ch + (size_t)(row + 8) * N + col) = v;
                    }
                } else {
                    float* Cf = (float*)J.C;
                    if (row < M)
                        *(float2*)(Cf + (size_t)row * N + col) = make_float2(v00, v01);
                    if (row + 8 < M)
                        *(float2*)(Cf + (size_t)(row + 8) * N + col) = make_float2(v10, v11);
                }
            }
        }
    }
}

// Heterogeneous combo: blocks [0, a.nblk) run job a; rest run job b.
__global__ __launch_bounds__(512)
void gemm_combo(GemmJob a, GemmJob b) {
    extern __shared__ char smem_raw[];
    const uint32_t sbase = (smem_u32(smem_raw) + 127) & ~127u;
    int bid = blockIdx.x;
    if (bid < a.nblk) {
        int bx = bid % a.gx, by = bid / a.gx;
        if (a.path == 0) gemm_big_body(a, bx, by, sbase);
        else             gemm_small_body(a, bx, by, sbase);
    } else {
        bid -= a.nblk;
        int bx = bid % b.gx, by = bid / b.gx;
        if (b.path == 0) gemm_big_body(b, bx, by, sbase);
        else             gemm_small_body(b, bx, by, sbase);
    }
}

// ---------------------------------------------------------------------------
// Fused leaf kernel (unchanged from R10). Writes Ch, Hh (fp16).
// ---------------------------------------------------------------------------
#define LF_PITCH 80
#define LF_AT (128 * LF_PITCH)
#define LF_BT (64 * LF_PITCH)
#define LF_STAGE (LF_AT + 3 * LF_BT)
#define LF_SMEM (3 * LF_STAGE + 128)

__global__ __launch_bounds__(512)
void leaf_fused(const hlf* __restrict__ Ah) {
    extern __shared__ char smem_raw[];
    const uint32_t sbase = (smem_u32(smem_raw) + 127) & ~127u;

    const int tid  = threadIdx.x;
    const int lane = tid & 31;
    const int wid  = tid >> 5;
    const int wm   = wid >> 2;
    const int wn   = wid & 3;
    const int bm   = blockIdx.y * 128;
    const int bh   = blockIdx.x * 64;
    const int K    = 512;
    const int NC   = 16;

    const int ag = lane >> 3, ai = lane & 7;
    const int a_row = ai + (ag & 1) * 8;
    const int a_kb  = (ag >> 1) * 16;
    const int b_row2 = (lane & 7) + ((lane >> 4) << 3);
    const int b_kb   = ((lane >> 3) & 1) * 16;

    float acc[3][2][2][4];
#pragma unroll
    for (int g = 0; g < 3; g++)
#pragma unroll
        for (int mt = 0; mt < 2; mt++)
#pragma unroll
            for (int nt = 0; nt < 2; nt++)
#pragma unroll
                for (int j = 0; j < 4; j++) acc[g][mt][nt][j] = 0.f;

    auto load_chunk = [&](int c, int s) {
        const uint32_t sb = sbase + s * LF_STAGE;
        const int k0 = c << 5;
        {
            int row = tid >> 2, cb = tid & 3;
            size_t aoff = (size_t)(bm + row) * K + k0 + cb * 8;
            cp16(sb + row * LF_PITCH + cb * 16, Ah + aoff);
        }
#pragma unroll
        for (int i = 0; i < 2; ++i) {
            int p = tid + i * 512;
            if (p < 768) {
                int g = p >> 8, pp = p & 255;
                int row = pp >> 2, cb = pp & 3;
                size_t woff = (size_t)(g * 512 + bh + row) * 512 + k0 + cb * 8;
                cp16(sb + LF_AT + g * LF_BT + row * LF_PITCH + cb * 16, g_Wlh + woff);
            }
        }
        CP_COMMIT();
    };

    load_chunk(0, 0);
    load_chunk(1, 1);

    for (int c = 0; c < NC; ++c) {
        if (c + 2 < NC) load_chunk(c + 2, (c + 2) % 3);

        if (c + 2 < NC)      asm volatile("cp.async.wait_group 2;" ::: "memory");
        else if (c + 1 < NC) asm volatile("cp.async.wait_group 1;" ::: "memory");
        else                 asm volatile("cp.async.wait_group 0;" ::: "memory");
        __syncthreads();

        const uint32_t sb = sbase + (c % 3) * LF_STAGE;

#pragma unroll
        for (int ks = 0; ks < 2; ++ks) {
            const int kb = ks * 32;
            uint32_t ah[2][4];
#pragma unroll
            for (int mt = 0; mt < 2; ++mt) {
                uint32_t ro = (wm * 32 + mt * 16 + a_row) * LF_PITCH + a_kb + kb;
                ldsm4(ah[mt], sb + ro);
            }
            uint32_t bg[3][4];
#pragma unroll
            for (int g = 0; g < 3; ++g) {
                uint32_t ro = (wn * 16 + b_row2) * LF_PITCH + b_kb + kb;
                ldsm4(bg[g], sb + LF_AT + g * LF_BT + ro);
            }
#pragma unroll
            for (int g = 0; g < 3; ++g)
#pragma unroll
                for (int mt = 0; mt < 2; ++mt)
#pragma unroll
                    for (int nt = 0; nt < 2; ++nt)
                        mma16816(acc[g][mt][nt], ah[mt], &bg[g][nt * 2]);
        }
        __syncthreads();
    }

    const int r0 = lane >> 2;
    const int q2 = (lane & 3) * 2;
#pragma unroll
    for (int mt = 0; mt < 2; ++mt) {
#pragma unroll
        for (int nt = 0; nt < 2; ++nt) {
            int col = bh + wn * 16 + nt * 8 + q2;
            float bi0 = g_bleaf[col],        bi1 = g_bleaf[col + 1];
            float bo0 = g_bleaf[512 + col],  bo1 = g_bleaf[512 + col + 1];
            float bu0 = g_bleaf[1024 + col], bu1 = g_bleaf[1024 + col + 1];
#pragma unroll
            for (int hf = 0; hf < 2; ++hf) {
                int row = bm + wm * 32 + mt * 16 + r0 + hf * 8;
                float i0 = sigf(acc[0][mt][nt][hf * 2 + 0] + bi0);
                float i1 = sigf(acc[0][mt][nt][hf * 2 + 1] + bi1);
                float o0 = sigf(acc[1][mt][nt][hf * 2 + 0] + bo0);
                float o1 = sigf(acc[1][mt][nt][hf * 2 + 1] + bo1);
                float u0 = tanhf(acc[2][mt][nt][hf * 2 + 0] + bu0);
                float u1 = tanhf(acc[2][mt][nt][hf * 2 + 1] + bu1);
                float c0 = i0 * u0, c1 = i1 * u1;
                float h0 = o0 * tanhf(c0), h1 = o1 * tanhf(c1);
                size_t gci = (size_t)(4369 + row) * HID + col;
                size_t ghi = (size_t)row * HID + col;
                __half2 vc; vc.x = __float2half_rn(c0); vc.y = __float2half_rn(c1);
                __half2 vh; vh.x = __float2half_rn(h0); vh.y = __float2half_rn(h1);
                *(__half2*)(g_Ch + gci) = vc;
                *(__half2*)(g_Hh + ghi) = vh;
            }
        }
    }
}

// ---------------------------------------------------------------------------
// prep: pack weights (blocks [0,8192)) || convert leaf x (blocks [8192,40960))
// ---------------------------------------------------------------------------
__global__ void prep(const float* __restrict__ wi_w, const float* __restrict__ wi_b,
                     const float* __restrict__ wf_w, const float* __restrict__ wf_b,
                     const float* __restrict__ wo_w, const float* __restrict__ wo_b,
                     const float* __restrict__ wu_w, const float* __restrict__ wu_b,
                     const float* __restrict__ xleaf) {
    if (blockIdx.x < 8192) {
        int idx = blockIdx.x * 256 + threadIdx.x;
        if (idx < 2048 * 1024) {
            int r = idx >> 10, k = idx & 1023;
            float v;
            if      (r <  512) v = wi_w[r * 1024 + k];
            else if (r < 1024) v = wo_w[(r -  512) * 1024 + k];
            else if (r < 1536) v = wu_w[(r - 1024) * 1024 + k];
            else               v = (k < 512) ? wf_w[(r - 1536) * 1024 + k] : 0.f;
            g_Wnh[idx] = __float2half_rn(v);
        }
        if (idx < 1536 * 512) {
            int r = idx >> 9, k = idx & 511;
            float v;
            if      (r <  512) v = wi_w[r * 1024 + k];
            else if (r < 1024) v = wo_w[(r -  512) * 1024 + k];
            else               v = wu_w[(r - 1024) * 1024 + k];
            g_Wlh[idx] = __float2half_rn(v);
        }
        if (idx < 512 * 512) {
            int r = idx >> 9, k = idx & 511;
            g_Wfhh[idx] = __float2half_rn(wf_w[r * 1024 + 512 + k]);
        }
        if (idx < 1536)
            g_bleaf[idx] = (idx < 512) ? wi_b[idx]
                         : (idx < 1024) ? wo_b[idx - 512] : wu_b[idx - 1024];
        if (idx < 2048)
            g_bnode[idx] = (idx <  512) ? wi_b[idx]
                         : (idx < 1024) ? wo_b[idx -  512]
                         : (idx < 1536) ? wu_b[idx - 1024] : wf_b[idx - 1536];
    } else {
        int i = (blockIdx.x - 8192) * 256 + threadIdx.x;   // < 8388608 exactly
        float4 v = ((const float4*)xleaf)[i];
        hlf hh[4];
        hh[0] = __float2half_rn(v.x); hh[1] = __float2half_rn(v.y);
        hh[2] = __float2half_rn(v.z); hh[3] = __float2half_rn(v.w);
        ((uint2*)g_Xh)[i] = *(uint2*)hh;
    }
}

// ---------------------------------------------------------------------------
// Elementwise stages (unchanged from R10)
// ---------------------------------------------------------------------------
__global__ void concat_xh4(const float* __restrict__ x, int off_d, int off_c,
                           int n, int leafkids) {
    int idx = blockIdx.x * blockDim.x + threadIdx.x;
    if (idx >= n * 256) return;
    int r = idx >> 8, c4 = (idx & 255) * 4;
    float4 v;
    if (c4 < 512) {
        v = *(const float4*)(x + (size_t)(off_d + r) * IN_DIM + c4);
    } else {
        int hc = c4 - 512;
        v = make_float4(0.f, 0.f, 0.f, 0.f);
        if (leafkids) {
            size_t base = (size_t)(off_c + r * 16 - 4369) * HID + hc;
#pragma unroll
            for (int k = 0; k < 16; k++) {
                float4 t = h4_to_f4(*(const uint2*)(g_Hh + base + k * HID));
                v.x += t.x; v.y += t.y; v.z += t.z; v.w += t.w;
            }
        } else {
            size_t base = (size_t)(off_c + r * 16) * HID + hc;
#pragma unroll
            for (int k = 0; k < 16; k++) {
                float4 t = *(const float4*)(g_H + base + k * HID);
                v.x += t.x; v.y += t.y; v.z += t.z; v.w += t.w;
            }
        }
    }
    hlf hh[4];
    hh[0] = __float2half_rn(v.x); hh[1] = __float2half_rn(v.y);
    hh[2] = __float2half_rn(v.z); hh[3] = __float2half_rn(v.w);
    *(uint2*)(g_XHh + (size_t)r * 1024 + c4) = *(uint2*)hh;
}

__global__ void node_epilogue4(int off_d, int off_c, int n, int leafkids) {
    int idx = blockIdx.x * blockDim.x + threadIdx.x;
    if (idx >= n * 128) return;
    int r = idx >> 7, h4 = (idx & 127) * 4;
    const float* g = g_G + (size_t)r * 2048;
    float4 gi = *(const float4*)(g + h4);
    float4 go = *(const float4*)(g + 512 + h4);
    float4 gu = *(const float4*)(g + 1024 + h4);
    float4 gf = *(const float4*)(g + 1536 + h4);
    float a0 = sigf(gi.x) * tanhf(gu.x);
    float a1 = sigf(gi.y) * tanhf(gu.y);
    float a2 = sigf(gi.z) * tanhf(gu.z);
    float a3 = sigf(gi.w) * tanhf(gu.w);
    size_t cb = (size_t)(off_c + r * 16) * HID + h4;
#pragma unroll
    for (int k = 0; k < 16; k++) {
        float4 fh = h4_to_f4(*(const uint2*)(g_FHh + cb + k * HID));
        float4 cc;
        if (leafkids) cc = h4_to_f4(*(const uint2*)(g_Ch + cb + k * HID));
        else          cc = *(const float4*)(g_C + cb + k * HID);
        a0 += sigf(gf.x + fh.x) * cc.x;
        a1 += sigf(gf.y + fh.y) * cc.y;
        a2 += sigf(gf.z + fh.z) * cc.z;
        a3 += sigf(gf.w + fh.w) * cc.w;
    }
    size_t gidx = (size_t)(off_d + r) * HID + h4;
    *(float4*)(g_C + gidx) = make_float4(a0, a1, a2, a3);
    float4 hv = make_float4(sigf(go.x) * tanhf(a0), sigf(go.y) * tanhf(a1),
                            sigf(go.z) * tanhf(a2), sigf(go.w) * tanhf(a3));
    *(float4*)(g_H + gidx) = hv;
    hlf hh[4];
    hh[0] = __float2half_rn(a0); hh[1] = __float2half_rn(a1);
    hh[2] = __float2half_rn(a2); hh[3] = __float2half_rn(a3);
    *(uint2*)(g_Ch + gidx) = *(uint2*)hh;
}

__global__ void writeout(float* __restrict__ out) {
    int idx = blockIdx.x * blockDim.x + threadIdx.x;
    if (idx < 512)       out[idx] = g_H[idx];
    else if (idx < 1024) out[idx] = g_C[idx - 512];
}

// ---------------------------------------------------------------------------
// Launch
// ---------------------------------------------------------------------------
static GemmJob mk_job(const hlf* A, const hlf* B, void* C, const float* bias,
                      int M, int N, int K, int half_out) {
    GemmJob j;
    j.A = A; j.B = B; j.C = C; j.bias = bias;
    j.M = M; j.N = N; j.K = K; j.half_out = half_out;
    if (M >= 1024) { j.path = 0; j.gx = N / 256; j.nblk = j.gx * ((M + 127) / 128); }
    else           { j.path = 1; j.gx = N / 64;  j.nblk = j.gx * ((M + 63) / 64);  }
    return j;
}

extern "C" void kernel_launch(void* const* d_in, const int* in_sizes, int n_in,
                              void* d_out, int out_size) {
    const float* x    = (const float*)d_in[0];
    const float* wi_w = (const float*)d_in[1];
    const float* wi_b = (const float*)d_in[2];
    const float* wf_w = (const float*)d_in[3];
    const float* wf_b = (const float*)d_in[4];
    const float* wo_w = (const float*)d_in[5];
    const float* wo_b = (const float*)d_in[6];
    const float* wu_w = (const float*)d_in[7];
    const float* wu_b = (const float*)d_in[8];
    float* out = (float*)d_out;

    cudaFuncSetAttribute(gemm_combo, cudaFuncAttributeMaxDynamicSharedMemorySize, GSMEM);
    cudaFuncSetAttribute(leaf_fused, cudaFuncAttributeMaxDynamicSharedMemorySize, LF_SMEM);

    float *pG, *pbn;
    hlf *pXh, *pCh, *pXHh, *pWnh, *pWfhh, *pFHh;
    cudaGetSymbolAddress((void**)&pG,    g_G);
    cudaGetSymbolAddress((void**)&pbn,   g_bnode);
    cudaGetSymbolAddress((void**)&pXh,   g_Xh);
    cudaGetSymbolAddress((void**)&pCh,   g_Ch);
    cudaGetSymbolAddress((void**)&pXHh,  g_XHh);
    cudaGetSymbolAddress((void**)&pWnh,  g_Wnh);
    cudaGetSymbolAddress((void**)&pWfhh, g_Wfhh);
    cudaGetSymbolAddress((void**)&pFHh,  g_FHh);

    static const int offs[6]  = {0, 1, 17, 273, 4369, 69905};
    static const int sizes[5] = {1, 16, 256, 4096, 65536};

    // 1) prep: weights -> fp16 || leaf x -> fp16
    prep<<<40960, 256>>>(wi_w, wi_b, wf_w, wf_b, wo_w, wo_b, wu_w, wu_b,
                         x + (size_t)offs[4] * IN_DIM);

    // 2) fused leaf gates (writes Ch, Hh)
    {
        dim3 grid(HID / 64, NLEAF / 128);
        leaf_fused<<<grid, 512, LF_SMEM>>>(pXh);
    }

    // 3) levels bottom-up; each level: concat, combo(gates_d || FH_{d+1}), epi
    for (int d = 3; d >= 0; d--) {
        int n = sizes[d];
        int leafkids = (d == 3) ? 1 : 0;
        concat_xh4<<<(n * 256 + 255) / 256, 256>>>(x, offs[d], offs[d + 1], n, leafkids);

        GemmJob gates = mk_job(pXHh, pWnh, pG, pbn, n, 2048, 1024, 0);
        int nc = sizes[d + 1];                         // children count
        GemmJob fh = mk_job(pCh + (size_t)offs[d + 1] * HID, pWfhh,
                            pFHh + (size_t)offs[d + 1] * HID, nullptr,
                            nc, 512, 512, 1);
        gemm_combo<<<gates.nblk + fh.nblk, 512, GSMEM>>>(gates, fh);

        node_epilogue4<<<(n * 128 + 255) / 256, 256>>>(offs[d], offs[d + 1], n, leafkids);
    }

    // 4) output: H[0] then C[0]
    writeout<<<4, 256>>>(out);
}

// round 12
// speedup vs baseline: 1.0405x; 1.0405x over previous
#include <cuda_runtime.h>
#include <cuda_fp16.h>
#include <math.h>
#include <stdint.h>

// ---------------------------------------------------------------------------
// CSTreeLSTM on GB300: single-term fp16 HMMA GEMMs (fp32 accumulate),
// fp16 cross-kernel intermediates. Big GEMM: 128x128 tile, 256 threads,
// 2 CTAs/SM (cross-CTA overlap of pipeline barriers).
// Tree: 16-ary, depth 4, IN=HID=512. Levels 1,16,256,4096,65536
// (offsets 0,1,17,273,4369; total 69905).
// ---------------------------------------------------------------------------

#define IN_DIM 512
#define HID    512
#define NLEAF  65536
#define NTOT   69905

typedef __half hlf;

// ------------------------------ device scratch ------------------------------
__device__ __align__(128) float g_C [NTOT * HID];
__device__ __align__(128) float g_H [NTOT * HID];
__device__ __align__(128) hlf   g_FHh[NTOT * HID];
__device__ __align__(128) float g_G [4096 * 2048];

__device__ __align__(128) hlf g_Xh [NLEAF * IN_DIM];
__device__ __align__(128) hlf g_Ch [NTOT * HID];
__device__ __align__(128) hlf g_Hh [NLEAF * HID];
__device__ __align__(128) hlf g_XHh[4096 * 1024];

__device__ __align__(128) hlf g_Wnh[2048 * 1024];
__device__ __align__(128) hlf g_Wlh[1536 * 512];
__device__ __align__(128) hlf g_Wfhh[512 * 512];
__device__ float g_bleaf[1536];
__device__ float g_bnode[2048];

__device__ __forceinline__ float sigf(float x) { return 1.f / (1.f + expf(-x)); }

// ------------------------------ PTX helpers ---------------------------------
__device__ __forceinline__ uint32_t smem_u32(const void* p) {
    uint32_t a;
    asm("{ .reg .u64 t; cvta.to.shared.u64 t, %1; cvt.u32.u64 %0, t; }" : "=r"(a) : "l"(p));
    return a;
}

__device__ __forceinline__ void cp16(uint32_t dst, const void* src) {
    asm volatile("cp.async.cg.shared.global [%0], [%1], 16;" :: "r"(dst), "l"(src));
}
#define CP_COMMIT() asm volatile("cp.async.commit_group;" ::: "memory")

__device__ __forceinline__ void ldsm4(uint32_t* r, uint32_t addr) {
    asm volatile("ldmatrix.sync.aligned.m8n8.x4.shared.b16 {%0,%1,%2,%3}, [%4];"
                 : "=r"(r[0]), "=r"(r[1]), "=r"(r[2]), "=r"(r[3]) : "r"(addr));
}
__device__ __forceinline__ void mma16816(float* d, const uint32_t* a, const uint32_t* b) {
    asm volatile(
        "mma.sync.aligned.m16n8k16.row.col.f32.f16.f16.f32 "
        "{%0,%1,%2,%3}, {%4,%5,%6,%7}, {%8,%9}, {%0,%1,%2,%3};"
        : "+f"(d[0]), "+f"(d[1]), "+f"(d[2]), "+f"(d[3])
        : "r"(a[0]), "r"(a[1]), "r"(a[2]), "r"(a[3]), "r"(b[0]), "r"(b[1]));
}

__device__ __forceinline__ float4 h4_to_f4(uint2 u) {
    __half2 lo = *(__half2*)&u.x, hi = *(__half2*)&u.y;
    float2 a = __half22float2(lo), b = __half22float2(hi);
    return make_float4(a.x, a.y, b.x, b.y);
}

// ---------------------------------------------------------------------------
// Big GEMM: CTA 128(M) x 128(N), 256 threads / 8 warps, warp tile 32x64,
// BK=32, 3-stage cp.async, 2 CTAs/SM. N%128==0, K%32==0; M guarded.
// ---------------------------------------------------------------------------
#define TPITCH 80
#define AT_B (128 * TPITCH)            // 10240
#define STAGE_B (2 * AT_B)             // 20480 (A + B)
#define GSMEM (3 * STAGE_B + 128)      // 61568

__global__ __launch_bounds__(256, 2)
void gemm_h(const hlf* __restrict__ Ah, const hlf* __restrict__ Bh,
            void* __restrict__ Cout, const float* __restrict__ bias,
            int M, int N, int K, int half_out) {
    extern __shared__ char smem_raw[];
    const uint32_t sbase = (smem_u32(smem_raw) + 127) & ~127u;

    const int tid  = threadIdx.x;
    const int lane = tid & 31;
    const int wid  = tid >> 5;          // 0..7
    const int wm   = wid >> 1;          // 0..3 (M slices of 32)
    const int wn   = wid & 1;           // 0..1 (N slices of 64)
    const int bm   = blockIdx.y * 128;
    const int bn   = blockIdx.x * 128;
    const int NC   = K >> 5;

    const int ag = lane >> 3, ai = lane & 7;
    const int a_row = ai + (ag & 1) * 8;
    const int a_kb  = (ag >> 1) * 16;
    const int b_row2 = (lane & 7) + ((lane >> 4) << 3);
    const int b_kb   = ((lane >> 3) & 1) * 16;

    float acc[2][8][4];
#pragma unroll
    for (int mt = 0; mt < 2; mt++)
#pragma unroll
        for (int nt = 0; nt < 8; nt++)
#pragma unroll
            for (int j = 0; j < 4; j++) acc[mt][nt][j] = 0.f;

    auto load_chunk = [&](int c, int s) {
        const uint32_t sb = sbase + s * STAGE_B;
        const int k0 = c << 5;
#pragma unroll
        for (int i = 0; i < 2; ++i) {
            int p = tid + i * 256;          // 512 positions per tile
            int row = p >> 2, cb = p & 3;
            int ar = bm + row; if (ar > M - 1) ar = M - 1;
            size_t aoff = (size_t)ar * K + k0 + cb * 8;
            size_t boff = (size_t)(bn + row) * K + k0 + cb * 8;
            uint32_t so = row * TPITCH + cb * 16;
            cp16(sb + so,        Ah + aoff);
            cp16(sb + AT_B + so, Bh + boff);
        }
        CP_COMMIT();
    };

    load_chunk(0, 0);
    if (NC > 1) load_chunk(1, 1);

    for (int c = 0; c < NC; ++c) {
        if (c + 2 < NC) load_chunk(c + 2, (c + 2) % 3);

        if (c + 2 < NC)      asm volatile("cp.async.wait_group 2;" ::: "memory");
        else if (c + 1 < NC) asm volatile("cp.async.wait_group 1;" ::: "memory");
        else                 asm volatile("cp.async.wait_group 0;" ::: "memory");
        __syncthreads();

        const uint32_t sb  = sbase + (c % 3) * STAGE_B;
        const uint32_t tAh = sb, tBh = sb + AT_B;

#pragma unroll
        for (int ks = 0; ks < 2; ++ks) {
            const int kb = ks * 32;
            uint32_t ah[2][4], bh[8][2];
#pragma unroll
            for (int mt = 0; mt < 2; ++mt) {
                uint32_t ro = (wm * 32 + mt * 16 + a_row) * TPITCH + a_kb + kb;
                ldsm4(ah[mt], tAh + ro);
            }
#pragma unroll
            for (int nt2 = 0; nt2 < 8; nt2 += 2) {
                uint32_t ro = (wn * 64 + nt2 * 8 + b_row2) * TPITCH + b_kb + kb;
                ldsm4(&bh[nt2][0], tBh + ro);
            }
#pragma unroll
            for (int mt = 0; mt < 2; ++mt)
#pragma unroll
                for (int nt = 0; nt < 8; ++nt)
                    mma16816(acc[mt][nt], ah[mt], bh[nt]);
        }
        __syncthreads();
    }

    const int r0 = lane >> 2;
    const int q2 = (lane & 3) * 2;
#pragma unroll
    for (int mt = 0; mt < 2; ++mt) {
        int row = bm + wm * 32 + mt * 16 + r0;
#pragma unroll
        for (int nt = 0; nt < 8; ++nt) {
            int col = bn + wn * 64 + nt * 8 + q2;
            float bx = 0.f, by = 0.f;
            if (bias) { bx = bias[col]; by = bias[col + 1]; }
            float v00 = acc[mt][nt][0] + bx, v01 = acc[mt][nt][1] + by;
            float v10 = acc[mt][nt][2] + bx, v11 = acc[mt][nt][3] + by;
            if (half_out) {
                hlf* Ch = (hlf*)Cout;
                if (row < M) {
                    __half2 v; v.x = __float2half_rn(v00); v.y = __float2half_rn(v01);
                    *(__half2*)(Ch + (size_t)row * N + col) = v;
                }
                if (row + 8 < M) {
                    __half2 v; v.x = __float2half_rn(v10); v.y = __float2half_rn(v11);
                    *(__half2*)(Ch + (size_t)(row + 8) * N + col) = v;
                }
            } else {
                float* Cf = (float*)Cout;
                if (row < M)
                    *(float2*)(Cf + (size_t)row * N + col) = make_float2(v00, v01);
                if (row + 8 < M)
                    *(float2*)(Cf + (size_t)(row + 8) * N + col) = make_float2(v10, v11);
            }
        }
    }
}

// ---------------------------------------------------------------------------
// fp16 GEMM, CTA 64x64 (small M tail). 128 threads, 4 warps 32x32.
// ---------------------------------------------------------------------------
#define G64_T (64 * TPITCH)
#define G64_STAGE (2 * G64_T)
#define G64_SMEM (3 * G64_STAGE + 128)

__global__ __launch_bounds__(128)
void gemm_h64(const hlf* __restrict__ Ah, const hlf* __restrict__ Bh,
              void* __restrict__ Cout, const float* __restrict__ bias,
              int M, int N, int K, int half_out) {
    extern __shared__ char smem_raw[];
    const uint32_t sbase = (smem_u32(smem_raw) + 127) & ~127u;

    const int tid  = threadIdx.x;
    const int lane = tid & 31;
    const int wid  = tid >> 5;
    const int wm   = wid >> 1;
    const int wn   = wid & 1;
    const int bm   = blockIdx.y * 64;
    const int bn   = blockIdx.x * 64;
    const int NC   = K >> 5;

    const int ag = lane >> 3, ai = lane & 7;
    const int a_row = ai + (ag & 1) * 8;
    const int a_kb  = (ag >> 1) * 16;
    const int b_row2 = (lane & 7) + ((lane >> 4) << 3);
    const int b_kb   = ((lane >> 3) & 1) * 16;

    float acc[2][4][4];
#pragma unroll
    for (int mt = 0; mt < 2; mt++)
#pragma unroll
        for (int nt = 0; nt < 4; nt++)
#pragma unroll
            for (int j = 0; j < 4; j++) acc[mt][nt][j] = 0.f;

    auto load_chunk = [&](int c, int s) {
        const uint32_t sb = sbase + s * G64_STAGE;
        const int k0 = c << 5;
#pragma unroll
        for (int it = 0; it < 2; ++it) {
            int idx = tid + it * 128;
            int row = idx >> 2, cb = idx & 3;
            int ar = bm + row; if (ar > M - 1) ar = M - 1;
            size_t aoff = (size_t)ar * K + k0 + cb * 8;
            size_t boff = (size_t)(bn + row) * K + k0 + cb * 8;
            uint32_t so = row * TPITCH + cb * 16;
            cp16(sb + so,         Ah + aoff);
            cp16(sb + G64_T + so, Bh + boff);
        }
        CP_COMMIT();
    };

    load_chunk(0, 0);
    if (NC > 1) load_chunk(1, 1);

    for (int c = 0; c < NC; ++c) {
        if (c + 2 < NC) load_chunk(c + 2, (c + 2) % 3);

        if (c + 2 < NC)      asm volatile("cp.async.wait_group 2;" ::: "memory");
        else if (c + 1 < NC) asm volatile("cp.async.wait_group 1;" ::: "memory");
        else                 asm volatile("cp.async.wait_group 0;" ::: "memory");
        __syncthreads();

        const uint32_t sb  = sbase + (c % 3) * G64_STAGE;
        const uint32_t tAh = sb, tBh = sb + G64_T;

#pragma unroll
        for (int ks = 0; ks < 2; ++ks) {
            const int kb = ks * 32;
            uint32_t ah[2][4], bh[4][2];
#pragma unroll
            for (int mt = 0; mt < 2; ++mt) {
                uint32_t ro = (wm * 32 + mt * 16 + a_row) * TPITCH + a_kb + kb;
                ldsm4(ah[mt], tAh + ro);
            }
#pragma unroll
            for (int nt2 = 0; nt2 < 4; nt2 += 2) {
                uint32_t ro = (wn * 32 + nt2 * 8 + b_row2) * TPITCH + b_kb + kb;
                ldsm4(&bh[nt2][0], tBh + ro);
            }
#pragma unroll
            for (int mt = 0; mt < 2; ++mt)
#pragma unroll
                for (int nt = 0; nt < 4; ++nt)
                    mma16816(acc[mt][nt], ah[mt], bh[nt]);
        }
        __syncthreads();
    }

    const int r0 = lane >> 2;
    const int q2 = (lane & 3) * 2;
#pragma unroll
    for (int mt = 0; mt < 2; ++mt) {
        int row = bm + wm * 32 + mt * 16 + r0;
#pragma unroll
        for (int nt = 0; nt < 4; ++nt) {
            int col = bn + wn * 32 + nt * 8 + q2;
            float bx = 0.f, by = 0.f;
            if (bias) { bx = bias[col]; by = bias[col + 1]; }
            float v00 = acc[mt][nt][0] + bx, v01 = acc[mt][nt][1] + by;
            float v10 = acc[mt][nt][2] + bx, v11 = acc[mt][nt][3] + by;
            if (half_out) {
                hlf* Ch = (hlf*)Cout;
                if (row < M) {
                    __half2 v; v.x = __float2half_rn(v00); v.y = __float2half_rn(v01);
                    *(__half2*)(Ch + (size_t)row * N + col) = v;
                }
                if (row + 8 < M) {
                    __half2 v; v.x = __float2half_rn(v10); v.y = __float2half_rn(v11);
                    *(__half2*)(Ch + (size_t)(row + 8) * N + col) = v;
                }
            } else {
                float* Cf = (float*)Cout;
                if (row < M)
                    *(float2*)(Cf + (size_t)row * N + col) = make_float2(v00, v01);
                if (row + 8 < M)
                    *(float2*)(Cf + (size_t)(row + 8) * N + col) = make_float2(v10, v11);
            }
        }
    }
}

// ---------------------------------------------------------------------------
// Fused leaf kernel (unchanged). Writes Ch, Hh (fp16).
// ---------------------------------------------------------------------------
#define LF_PITCH 80
#define LF_AT (128 * LF_PITCH)
#define LF_BT (64 * LF_PITCH)
#define LF_STAGE (LF_AT + 3 * LF_BT)
#define LF_SMEM (3 * LF_STAGE + 128)

__global__ __launch_bounds__(512)
void leaf_fused(const hlf* __restrict__ Ah) {
    extern __shared__ char smem_raw[];
    const uint32_t sbase = (smem_u32(smem_raw) + 127) & ~127u;

    const int tid  = threadIdx.x;
    const int lane = tid & 31;
    const int wid  = tid >> 5;
    const int wm   = wid >> 2;
    const int wn   = wid & 3;
    const int bm   = blockIdx.y * 128;
    const int bh   = blockIdx.x * 64;
    const int K    = 512;
    const int NC   = 16;

    const int ag = lane >> 3, ai = lane & 7;
    const int a_row = ai + (ag & 1) * 8;
    const int a_kb  = (ag >> 1) * 16;
    const int b_row2 = (lane & 7) + ((lane >> 4) << 3);
    const int b_kb   = ((lane >> 3) & 1) * 16;

    float acc[3][2][2][4];
#pragma unroll
    for (int g = 0; g < 3; g++)
#pragma unroll
        for (int mt = 0; mt < 2; mt++)
#pragma unroll
            for (int nt = 0; nt < 2; nt++)
#pragma unroll
                for (int j = 0; j < 4; j++) acc[g][mt][nt][j] = 0.f;

    auto load_chunk = [&](int c, int s) {
        const uint32_t sb = sbase + s * LF_STAGE;
        const int k0 = c << 5;
        {
            int row = tid >> 2, cb = tid & 3;
            size_t aoff = (size_t)(bm + row) * K + k0 + cb * 8;
            cp16(sb + row * LF_PITCH + cb * 16, Ah + aoff);
        }
#pragma unroll
        for (int i = 0; i < 2; ++i) {
            int p = tid + i * 512;
            if (p < 768) {
                int g = p >> 8, pp = p & 255;
                int row = pp >> 2, cb = pp & 3;
                size_t woff = (size_t)(g * 512 + bh + row) * 512 + k0 + cb * 8;
                cp16(sb + LF_AT + g * LF_BT + row * LF_PITCH + cb * 16, g_Wlh + woff);
            }
        }
        CP_COMMIT();
    };

    load_chunk(0, 0);
    load_chunk(1, 1);

    for (int c = 0; c < NC; ++c) {
        if (c + 2 < NC) load_chunk(c + 2, (c + 2) % 3);

        if (c + 2 < NC)      asm volatile("cp.async.wait_group 2;" ::: "memory");
        else if (c + 1 < NC) asm volatile("cp.async.wait_group 1;" ::: "memory");
        else                 asm volatile("cp.async.wait_group 0;" ::: "memory");
        __syncthreads();

        const uint32_t sb = sbase + (c % 3) * LF_STAGE;

#pragma unroll
        for (int ks = 0; ks < 2; ++ks) {
            const int kb = ks * 32;
            uint32_t ah[2][4];
#pragma unroll
            for (int mt = 0; mt < 2; ++mt) {
                uint32_t ro = (wm * 32 + mt * 16 + a_row) * LF_PITCH + a_kb + kb;
                ldsm4(ah[mt], sb + ro);
            }
            uint32_t bg[3][4];
#pragma unroll
            for (int g = 0; g < 3; ++g) {
                uint32_t ro = (wn * 16 + b_row2) * LF_PITCH + b_kb + kb;
                ldsm4(bg[g], sb + LF_AT + g * LF_BT + ro);
            }
#pragma unroll
            for (int g = 0; g < 3; ++g)
#pragma unroll
                for (int mt = 0; mt < 2; ++mt)
#pragma unroll
                    for (int nt = 0; nt < 2; ++nt)
                        mma16816(acc[g][mt][nt], ah[mt], &bg[g][nt * 2]);
        }
        __syncthreads();
    }

    const int r0 = lane >> 2;
    const int q2 = (lane & 3) * 2;
#pragma unroll
    for (int mt = 0; mt < 2; ++mt) {
#pragma unroll
        for (int nt = 0; nt < 2; ++nt) {
            int col = bh + wn * 16 + nt * 8 + q2;
            float bi0 = g_bleaf[col],        bi1 = g_bleaf[col + 1];
            float bo0 = g_bleaf[512 + col],  bo1 = g_bleaf[512 + col + 1];
            float bu0 = g_bleaf[1024 + col], bu1 = g_bleaf[1024 + col + 1];
#pragma unroll
            for (int hf = 0; hf < 2; ++hf) {
                int row = bm + wm * 32 + mt * 16 + r0 + hf * 8;
                float i0 = sigf(acc[0][mt][nt][hf * 2 + 0] + bi0);
                float i1 = sigf(acc[0][mt][nt][hf * 2 + 1] + bi1);
                float o0 = sigf(acc[1][mt][nt][hf * 2 + 0] + bo0);
                float o1 = sigf(acc[1][mt][nt][hf * 2 + 1] + bo1);
                float u0 = tanhf(acc[2][mt][nt][hf * 2 + 0] + bu0);
                float u1 = tanhf(acc[2][mt][nt][hf * 2 + 1] + bu1);
                float c0 = i0 * u0, c1 = i1 * u1;
                float h0 = o0 * tanhf(c0), h1 = o1 * tanhf(c1);
                size_t gci = (size_t)(4369 + row) * HID + col;
                size_t ghi = (size_t)row * HID + col;
                __half2 vc; vc.x = __float2half_rn(c0); vc.y = __float2half_rn(c1);
                __half2 vh; vh.x = __float2half_rn(h0); vh.y = __float2half_rn(h1);
                *(__half2*)(g_Ch + gci) = vc;
                *(__half2*)(g_Hh + ghi) = vh;
            }
        }
    }
}

// ---------------------------------------------------------------------------
// prep: pack weights (blocks [0,8192)) || convert leaf x (blocks [8192,40960))
// ---------------------------------------------------------------------------
__global__ void prep(const float* __restrict__ wi_w, const float* __restrict__ wi_b,
                     const float* __restrict__ wf_w, const float* __restrict__ wf_b,
                     const float* __restrict__ wo_w, const float* __restrict__ wo_b,
                     const float* __restrict__ wu_w, const float* __restrict__ wu_b,
                     const float* __restrict__ xleaf) {
    if (blockIdx.x < 8192) {
        int idx = blockIdx.x * 256 + threadIdx.x;
        if (idx < 2048 * 1024) {
            int r = idx >> 10, k = idx & 1023;
            float v;
            if      (r <  512) v = wi_w[r * 1024 + k];
            else if (r < 1024) v = wo_w[(r -  512) * 1024 + k];
            else if (r < 1536) v = wu_w[(r - 1024) * 1024 + k];
            else               v = (k < 512) ? wf_w[(r - 1536) * 1024 + k] : 0.f;
            g_Wnh[idx] = __float2half_rn(v);
        }
        if (idx < 1536 * 512) {
            int r = idx >> 9, k = idx & 511;
            float v;
            if      (r <  512) v = wi_w[r * 1024 + k];
            else if (r < 1024) v = wo_w[(r -  512) * 1024 + k];
            else               v = wu_w[(r - 1024) * 1024 + k];
            g_Wlh[idx] = __float2half_rn(v);
        }
        if (idx < 512 * 512) {
            int r = idx >> 9, k = idx & 511;
            g_Wfhh[idx] = __float2half_rn(wf_w[r * 1024 + 512 + k]);
        }
        if (idx < 1536)
            g_bleaf[idx] = (idx < 512) ? wi_b[idx]
                         : (idx < 1024) ? wo_b[idx - 512] : wu_b[idx - 1024];
        if (idx < 2048)
            g_bnode[idx] = (idx <  512) ? wi_b[idx]
                         : (idx < 1024) ? wo_b[idx -  512]
                         : (idx < 1536) ? wu_b[idx - 1024] : wf_b[idx - 1536];
    } else {
        int i = (blockIdx.x - 8192) * 256 + threadIdx.x;
        float4 v = ((const float4*)xleaf)[i];
        hlf hh[4];
        hh[0] = __float2half_rn(v.x); hh[1] = __float2half_rn(v.y);
        hh[2] = __float2half_rn(v.z); hh[3] = __float2half_rn(v.w);
        ((uint2*)g_Xh)[i] = *(uint2*)hh;
    }
}

// ---------------------------------------------------------------------------
// Elementwise stages
// ---------------------------------------------------------------------------
__global__ void concat_xh4(const float* __restrict__ x, int off_d, int off_c,
                           int n, int leafkids) {
    int idx = blockIdx.x * blockDim.x + threadIdx.x;
    if (idx >= n * 256) return;
    int r = idx >> 8, c4 = (idx & 255) * 4;
    float4 v;
    if (c4 < 512) {
        v = *(const float4*)(x + (size_t)(off_d + r) * IN_DIM + c4);
    } else {
        int hc = c4 - 512;
        v = make_float4(0.f, 0.f, 0.f, 0.f);
        if (leafkids) {
            size_t base = (size_t)(off_c + r * 16 - 4369) * HID + hc;
#pragma unroll
            for (int k = 0; k < 16; k++) {
                float4 t = h4_to_f4(*(const uint2*)(g_Hh + base + k * HID));
                v.x += t.x; v.y += t.y; v.z += t.z; v.w += t.w;
            }
        } else {
            size_t base = (size_t)(off_c + r * 16) * HID + hc;
#pragma unroll
            for (int k = 0; k < 16; k++) {
                float4 t = *(const float4*)(g_H + base + k * HID);
                v.x += t.x; v.y += t.y; v.z += t.z; v.w += t.w;
            }
        }
    }
    hlf hh[4];
    hh[0] = __float2half_rn(v.x); hh[1] = __float2half_rn(v.y);
    hh[2] = __float2half_rn(v.z); hh[3] = __float2half_rn(v.w);
    *(uint2*)(g_XHh + (size_t)r * 1024 + c4) = *(uint2*)hh;
}

__global__ void node_epilogue4(int off_d, int off_c, int n, int leafkids) {
    int idx = blockIdx.x * blockDim.x + threadIdx.x;
    if (idx >= n * 128) return;
    int r = idx >> 7, h4 = (idx & 127) * 4;
    const float* g = g_G + (size_t)r * 2048;
    float4 gi = *(const float4*)(g + h4);
    float4 go = *(const float4*)(g + 512 + h4);
    float4 gu = *(const float4*)(g + 1024 + h4);
    float4 gf = *(const float4*)(g + 1536 + h4);
    float a0 = sigf(gi.x) * tanhf(gu.x);
    float a1 = sigf(gi.y) * tanhf(gu.y);
    float a2 = sigf(gi.z) * tanhf(gu.z);
    float a3 = sigf(gi.w) * tanhf(gu.w);
    size_t cb = (size_t)(off_c + r * 16) * HID + h4;
#pragma unroll
    for (int k = 0; k < 16; k++) {
        float4 fh = h4_to_f4(*(const uint2*)(g_FHh + cb + k * HID));
        float4 cc;
        if (leafkids) cc = h4_to_f4(*(const uint2*)(g_Ch + cb + k * HID));
        else          cc = *(const float4*)(g_C + cb + k * HID);
        a0 += sigf(gf.x + fh.x) * cc.x;
        a1 += sigf(gf.y + fh.y) * cc.y;
        a2 += sigf(gf.z + fh.z) * cc.z;
        a3 += sigf(gf.w + fh.w) * cc.w;
    }
    size_t gidx = (size_t)(off_d + r) * HID + h4;
    *(float4*)(g_C + gidx) = make_float4(a0, a1, a2, a3);
    float4 hv = make_float4(sigf(go.x) * tanhf(a0), sigf(go.y) * tanhf(a1),
                            sigf(go.z) * tanhf(a2), sigf(go.w) * tanhf(a3));
    *(float4*)(g_H + gidx) = hv;
    hlf hh[4];
    hh[0] = __float2half_rn(a0); hh[1] = __float2half_rn(a1);
    hh[2] = __float2half_rn(a2); hh[3] = __float2half_rn(a3);
    *(uint2*)(g_Ch + gidx) = *(uint2*)hh;
}

__global__ void writeout(float* __restrict__ out) {
    int idx = blockIdx.x * blockDim.x + threadIdx.x;
    if (idx < 512)       out[idx] = g_H[idx];
    else if (idx < 1024) out[idx] = g_C[idx - 512];
}

// ---------------------------------------------------------------------------
// Launch
// ---------------------------------------------------------------------------
static void launch_gemm(const hlf* Ah, const hlf* Bh, void* Cout,
                        const float* bias, int M, int N, int K, int half_out) {
    if (M >= 1024) {
        dim3 grid(N / 128, (M + 127) / 128);
        gemm_h<<<grid, 256, GSMEM>>>(Ah, Bh, Cout, bias, M, N, K, half_out);
    } else {
        dim3 grid(N / 64, (M + 63) / 64);
        gemm_h64<<<grid, 128, G64_SMEM>>>(Ah, Bh, Cout, bias, M, N, K, half_out);
    }
}

extern "C" void kernel_launch(void* const* d_in, const int* in_sizes, int n_in,
                              void* d_out, int out_size) {
    const float* x    = (const float*)d_in[0];
    const float* wi_w = (const float*)d_in[1];
    const float* wi_b = (const float*)d_in[2];
    const float* wf_w = (const float*)d_in[3];
    const float* wf_b = (const float*)d_in[4];
    const float* wo_w = (const float*)d_in[5];
    const float* wo_b = (const float*)d_in[6];
    const float* wu_w = (const float*)d_in[7];
    const float* wu_b = (const float*)d_in[8];
    float* out = (float*)d_out;

    cudaFuncSetAttribute(gemm_h,     cudaFuncAttributeMaxDynamicSharedMemorySize, GSMEM);
    cudaFuncSetAttribute(gemm_h64,   cudaFuncAttributeMaxDynamicSharedMemorySize, G64_SMEM);
    cudaFuncSetAttribute(leaf_fused, cudaFuncAttributeMaxDynamicSharedMemorySize, LF_SMEM);

    float *pG, *pbn;
    hlf *pXh, *pCh, *pXHh, *pWnh, *pWfhh, *pFHh;
    cudaGetSymbolAddress((void**)&pG,    g_G);
    cudaGetSymbolAddress((void**)&pbn,   g_bnode);
    cudaGetSymbolAddress((void**)&pXh,   g_Xh);
    cudaGetSymbolAddress((void**)&pCh,   g_Ch);
    cudaGetSymbolAddress((void**)&pXHh,  g_XHh);
    cudaGetSymbolAddress((void**)&pWnh,  g_Wnh);
    cudaGetSymbolAddress((void**)&pWfhh, g_Wfhh);
    cudaGetSymbolAddress((void**)&pFHh,  g_FHh);

    static const int offs[6]  = {0, 1, 17, 273, 4369, 69905};
    static const int sizes[5] = {1, 16, 256, 4096, 65536};

    // 1) prep: weights -> fp16 || leaf x -> fp16
    prep<<<40960, 256>>>(wi_w, wi_b, wf_w, wf_b, wo_w, wo_b, wu_w, wu_b,
                         x + (size_t)offs[4] * IN_DIM);

    // 2) fused leaf gates (writes Ch, Hh), then FH GEMM (fp16 out)
    {
        dim3 grid(HID / 64, NLEAF / 128);
        leaf_fused<<<grid, 512, LF_SMEM>>>(pXh);
    }
    launch_gemm(pCh + (size_t)offs[4] * HID, pWfhh,
                pFHh + (size_t)offs[4] * HID, nullptr, NLEAF, 512, 512, 1);

    // 3) internal levels, bottom-up
    for (int d = 3; d >= 0; d--) {
        int n = sizes[d];
        int leafkids = (d == 3) ? 1 : 0;
        concat_xh4<<<(n * 256 + 255) / 256, 256>>>(x, offs[d], offs[d + 1], n, leafkids);
        launch_gemm(pXHh, pWnh, pG, pbn, n, 2048, 1024, 0);
        node_epilogue4<<<(n * 128 + 255) / 256, 256>>>(offs[d], offs[d + 1], n, leafkids);
        if (d > 0)
            launch_gemm(pCh + (size_t)offs[d] * HID, pWfhh,
                        pFHh + (size_t)offs[d] * HID, nullptr, n, 512, 512, 1);
    }

    // 4) output: H[0] then C[0]
    writeout<<<4, 256>>>(out);
}

// round 13
// speedup vs baseline: 1.1380x; 1.0938x over previous
#include <cuda_runtime.h>
#include <cuda_fp16.h>
#include <math.h>
#include <stdint.h>

// ---------------------------------------------------------------------------
// CSTreeLSTM on GB300: single-term fp16 HMMA GEMMs (fp32 accumulate),
// fp16 cross-kernel intermediates. BK=64 (half the barriers), big GEMM
// 128x128 @ 256 threads with 2 CTAs/SM.
// Tree: 16-ary, depth 4, IN=HID=512. Levels 1,16,256,4096,65536
// (offsets 0,1,17,273,4369; total 69905).
// ---------------------------------------------------------------------------

#define IN_DIM 512
#define HID    512
#define NLEAF  65536
#define NTOT   69905

typedef __half hlf;

// ------------------------------ device scratch ------------------------------
__device__ __align__(128) float g_C [NTOT * HID];
__device__ __align__(128) float g_H [NTOT * HID];
__device__ __align__(128) hlf   g_FHh[NTOT * HID];
__device__ __align__(128) float g_G [4096 * 2048];

__device__ __align__(128) hlf g_Xh [NLEAF * IN_DIM];
__device__ __align__(128) hlf g_Ch [NTOT * HID];
__device__ __align__(128) hlf g_Hh [NLEAF * HID];
__device__ __align__(128) hlf g_XHh[4096 * 1024];

__device__ __align__(128) hlf g_Wnh[2048 * 1024];
__device__ __align__(128) hlf g_Wlh[1536 * 512];
__device__ __align__(128) hlf g_Wfhh[512 * 512];
__device__ float g_bleaf[1536];
__device__ float g_bnode[2048];

__device__ __forceinline__ float sigf(float x) { return 1.f / (1.f + expf(-x)); }

// ------------------------------ PTX helpers ---------------------------------
__device__ __forceinline__ uint32_t smem_u32(const void* p) {
    uint32_t a;
    asm("{ .reg .u64 t; cvta.to.shared.u64 t, %1; cvt.u32.u64 %0, t; }" : "=r"(a) : "l"(p));
    return a;
}

__device__ __forceinline__ void cp16(uint32_t dst, const void* src) {
    asm volatile("cp.async.cg.shared.global [%0], [%1], 16;" :: "r"(dst), "l"(src));
}
#define CP_COMMIT() asm volatile("cp.async.commit_group;" ::: "memory")

__device__ __forceinline__ void ldsm4(uint32_t* r, uint32_t addr) {
    asm volatile("ldmatrix.sync.aligned.m8n8.x4.shared.b16 {%0,%1,%2,%3}, [%4];"
                 : "=r"(r[0]), "=r"(r[1]), "=r"(r[2]), "=r"(r[3]) : "r"(addr));
}
__device__ __forceinline__ void mma16816(float* d, const uint32_t* a, const uint32_t* b) {
    asm volatile(
        "mma.sync.aligned.m16n8k16.row.col.f32.f16.f16.f32 "
        "{%0,%1,%2,%3}, {%4,%5,%6,%7}, {%8,%9}, {%0,%1,%2,%3};"
        : "+f"(d[0]), "+f"(d[1]), "+f"(d[2]), "+f"(d[3])
        : "r"(a[0]), "r"(a[1]), "r"(a[2]), "r"(a[3]), "r"(b[0]), "r"(b[1]));
}

__device__ __forceinline__ float4 h4_to_f4(uint2 u) {
    __half2 lo = *(__half2*)&u.x, hi = *(__half2*)&u.y;
    float2 a = __half22float2(lo), b = __half22float2(hi);
    return make_float4(a.x, a.y, b.x, b.y);
}

// ---------------------------------------------------------------------------
// Big GEMM: CTA 128(M) x 128(N), 256 threads / 8 warps, warp tile 32x64,
// BK=64, 3-stage cp.async, 2 CTAs/SM. N%128==0, K%64==0; M guarded.
// Row pitch 144B (64 fp16 + 16B pad): conflict-free ldsm.
// ---------------------------------------------------------------------------
#define TP144 144
#define AT_B (128 * TP144)             // 18432
#define STAGE_B (2 * AT_B)             // 36864 (A + B)
#define GSMEM (3 * STAGE_B + 128)      // 110720

__global__ __launch_bounds__(256, 2)
void gemm_h(const hlf* __restrict__ Ah, const hlf* __restrict__ Bh,
            void* __restrict__ Cout, const float* __restrict__ bias,
            int M, int N, int K, int half_out) {
    extern __shared__ char smem_raw[];
    const uint32_t sbase = (smem_u32(smem_raw) + 127) & ~127u;

    const int tid  = threadIdx.x;
    const int lane = tid & 31;
    const int wid  = tid >> 5;          // 0..7
    const int wm   = wid >> 1;          // 0..3 (M slices of 32)
    const int wn   = wid & 1;           // 0..1 (N slices of 64)
    const int bm   = blockIdx.y * 128;
    const int bn   = blockIdx.x * 128;
    const int NC   = K >> 6;

    const int ag = lane >> 3, ai = lane & 7;
    const int a_row = ai + (ag & 1) * 8;
    const int a_kb  = (ag >> 1) * 16;
    const int b_row2 = (lane & 7) + ((lane >> 4) << 3);
    const int b_kb   = ((lane >> 3) & 1) * 16;

    float acc[2][8][4];
#pragma unroll
    for (int mt = 0; mt < 2; mt++)
#pragma unroll
        for (int nt = 0; nt < 8; nt++)
#pragma unroll
            for (int j = 0; j < 4; j++) acc[mt][nt][j] = 0.f;

    auto load_chunk = [&](int c, int s) {
        const uint32_t sb = sbase + s * STAGE_B;
        const int k0 = c << 6;
#pragma unroll
        for (int i = 0; i < 4; ++i) {
            int p = tid + i * 256;          // 1024 positions per tile
            int row = p >> 3, cb = p & 7;
            int ar = bm + row; if (ar > M - 1) ar = M - 1;
            size_t aoff = (size_t)ar * K + k0 + cb * 8;
            size_t boff = (size_t)(bn + row) * K + k0 + cb * 8;
            uint32_t so = row * TP144 + cb * 16;
            cp16(sb + so,        Ah + aoff);
            cp16(sb + AT_B + so, Bh + boff);
        }
        CP_COMMIT();
    };

    load_chunk(0, 0);
    if (NC > 1) load_chunk(1, 1);

    for (int c = 0; c < NC; ++c) {
        if (c + 2 < NC) load_chunk(c + 2, (c + 2) % 3);

        if (c + 2 < NC)      asm volatile("cp.async.wait_group 2;" ::: "memory");
        else if (c + 1 < NC) asm volatile("cp.async.wait_group 1;" ::: "memory");
        else                 asm volatile("cp.async.wait_group 0;" ::: "memory");
        __syncthreads();

        const uint32_t sb  = sbase + (c % 3) * STAGE_B;
        const uint32_t tAh = sb, tBh = sb + AT_B;

#pragma unroll
        for (int ks = 0; ks < 4; ++ks) {
            const int kb = ks * 32;
            uint32_t ah[2][4], bh[8][2];
#pragma unroll
            for (int mt = 0; mt < 2; ++mt) {
                uint32_t ro = (wm * 32 + mt * 16 + a_row) * TP144 + a_kb + kb;
                ldsm4(ah[mt], tAh + ro);
            }
#pragma unroll
            for (int nt2 = 0; nt2 < 8; nt2 += 2) {
                uint32_t ro = (wn * 64 + nt2 * 8 + b_row2) * TP144 + b_kb + kb;
                ldsm4(&bh[nt2][0], tBh + ro);
            }
#pragma unroll
            for (int mt = 0; mt < 2; ++mt)
#pragma unroll
                for (int nt = 0; nt < 8; ++nt)
                    mma16816(acc[mt][nt], ah[mt], bh[nt]);
        }
        __syncthreads();
    }

    const int r0 = lane >> 2;
    const int q2 = (lane & 3) * 2;
#pragma unroll
    for (int mt = 0; mt < 2; ++mt) {
        int row = bm + wm * 32 + mt * 16 + r0;
#pragma unroll
        for (int nt = 0; nt < 8; ++nt) {
            int col = bn + wn * 64 + nt * 8 + q2;
            float bx = 0.f, by = 0.f;
            if (bias) { bx = bias[col]; by = bias[col + 1]; }
            float v00 = acc[mt][nt][0] + bx, v01 = acc[mt][nt][1] + by;
            float v10 = acc[mt][nt][2] + bx, v11 = acc[mt][nt][3] + by;
            if (half_out) {
                hlf* Ch = (hlf*)Cout;
                if (row < M) {
                    __half2 v; v.x = __float2half_rn(v00); v.y = __float2half_rn(v01);
                    *(__half2*)(Ch + (size_t)row * N + col) = v;
                }
                if (row + 8 < M) {
                    __half2 v; v.x = __float2half_rn(v10); v.y = __float2half_rn(v11);
                    *(__half2*)(Ch + (size_t)(row + 8) * N + col) = v;
                }
            } else {
                float* Cf = (float*)Cout;
                if (row < M)
                    *(float2*)(Cf + (size_t)row * N + col) = make_float2(v00, v01);
                if (row + 8 < M)
                    *(float2*)(Cf + (size_t)(row + 8) * N + col) = make_float2(v10, v11);
            }
        }
    }
}

// ---------------------------------------------------------------------------
// fp16 GEMM, CTA 64x64 (small M tail). 128 threads, 4 warps 32x32. BK=32.
// ---------------------------------------------------------------------------
#define TPITCH 80
#define G64_T (64 * TPITCH)
#define G64_STAGE (2 * G64_T)
#define G64_SMEM (3 * G64_STAGE + 128)

__global__ __launch_bounds__(128)
void gemm_h64(const hlf* __restrict__ Ah, const hlf* __restrict__ Bh,
              void* __restrict__ Cout, const float* __restrict__ bias,
              int M, int N, int K, int half_out) {
    extern __shared__ char smem_raw[];
    const uint32_t sbase = (smem_u32(smem_raw) + 127) & ~127u;

    const int tid  = threadIdx.x;
    const int lane = tid & 31;
    const int wid  = tid >> 5;
    const int wm   = wid >> 1;
    const int wn   = wid & 1;
    const int bm   = blockIdx.y * 64;
    const int bn   = blockIdx.x * 64;
    const int NC   = K >> 5;

    const int ag = lane >> 3, ai = lane & 7;
    const int a_row = ai + (ag & 1) * 8;
    const int a_kb  = (ag >> 1) * 16;
    const int b_row2 = (lane & 7) + ((lane >> 4) << 3);
    const int b_kb   = ((lane >> 3) & 1) * 16;

    float acc[2][4][4];
#pragma unroll
    for (int mt = 0; mt < 2; mt++)
#pragma unroll
        for (int nt = 0; nt < 4; nt++)
#pragma unroll
            for (int j = 0; j < 4; j++) acc[mt][nt][j] = 0.f;

    auto load_chunk = [&](int c, int s) {
        const uint32_t sb = sbase + s * G64_STAGE;
        const int k0 = c << 5;
#pragma unroll
        for (int it = 0; it < 2; ++it) {
            int idx = tid + it * 128;
            int row = idx >> 2, cb = idx & 3;
            int ar = bm + row; if (ar > M - 1) ar = M - 1;
            size_t aoff = (size_t)ar * K + k0 + cb * 8;
            size_t boff = (size_t)(bn + row) * K + k0 + cb * 8;
            uint32_t so = row * TPITCH + cb * 16;
            cp16(sb + so,         Ah + aoff);
            cp16(sb + G64_T + so, Bh + boff);
        }
        CP_COMMIT();
    };

    load_chunk(0, 0);
    if (NC > 1) load_chunk(1, 1);

    for (int c = 0; c < NC; ++c) {
        if (c + 2 < NC) load_chunk(c + 2, (c + 2) % 3);

        if (c + 2 < NC)      asm volatile("cp.async.wait_group 2;" ::: "memory");
        else if (c + 1 < NC) asm volatile("cp.async.wait_group 1;" ::: "memory");
        else                 asm volatile("cp.async.wait_group 0;" ::: "memory");
        __syncthreads();

        const uint32_t sb  = sbase + (c % 3) * G64_STAGE;
        const uint32_t tAh = sb, tBh = sb + G64_T;

#pragma unroll
        for (int ks = 0; ks < 2; ++ks) {
            const int kb = ks * 32;
            uint32_t ah[2][4], bh[4][2];
#pragma unroll
            for (int mt = 0; mt < 2; ++mt) {
                uint32_t ro = (wm * 32 + mt * 16 + a_row) * TPITCH + a_kb + kb;
                ldsm4(ah[mt], tAh + ro);
            }
#pragma unroll
            for (int nt2 = 0; nt2 < 4; nt2 += 2) {
                uint32_t ro = (wn * 32 + nt2 * 8 + b_row2) * TPITCH + b_kb + kb;
                ldsm4(&bh[nt2][0], tBh + ro);
            }
#pragma unroll
            for (int mt = 0; mt < 2; ++mt)
#pragma unroll
                for (int nt = 0; nt < 4; ++nt)
                    mma16816(acc[mt][nt], ah[mt], bh[nt]);
        }
        __syncthreads();
    }

    const int r0 = lane >> 2;
    const int q2 = (lane & 3) * 2;
#pragma unroll
    for (int mt = 0; mt < 2; ++mt) {
        int row = bm + wm * 32 + mt * 16 + r0;
#pragma unroll
        for (int nt = 0; nt < 4; ++nt) {
            int col = bn + wn * 32 + nt * 8 + q2;
            float bx = 0.f, by = 0.f;
            if (bias) { bx = bias[col]; by = bias[col + 1]; }
            float v00 = acc[mt][nt][0] + bx, v01 = acc[mt][nt][1] + by;
            float v10 = acc[mt][nt][2] + bx, v11 = acc[mt][nt][3] + by;
            if (half_out) {
                hlf* Ch = (hlf*)Cout;
                if (row < M) {
                    __half2 v; v.x = __float2half_rn(v00); v.y = __float2half_rn(v01);
                    *(__half2*)(Ch + (size_t)row * N + col) = v;
                }
                if (row + 8 < M) {
                    __half2 v; v.x = __float2half_rn(v10); v.y = __float2half_rn(v11);
                    *(__half2*)(Ch + (size_t)(row + 8) * N + col) = v;
                }
            } else {
                float* Cf = (float*)Cout;
                if (row < M)
                    *(float2*)(Cf + (size_t)row * N + col) = make_float2(v00, v01);
                if (row + 8 < M)
                    *(float2*)(Cf + (size_t)(row + 8) * N + col) = make_float2(v10, v11);
            }
        }
    }
}

// ---------------------------------------------------------------------------
// Fused leaf kernel. CTA 128(M) x 64(h) x 3 gates, 512 threads / 16 warps,
// warp tile 32x16 per gate, BK=64, 3 stages. Writes Ch, Hh (fp16).
// ---------------------------------------------------------------------------
#define LF_AT (128 * TP144)             // 18432
#define LF_BT (64 * TP144)              // 9216
#define LF_STAGE (LF_AT + 3 * LF_BT)    // 46080
#define LF_SMEM (3 * LF_STAGE + 128)    // 138368

__global__ __launch_bounds__(512)
void leaf_fused(const hlf* __restrict__ Ah) {
    extern __shared__ char smem_raw[];
    const uint32_t sbase = (smem_u32(smem_raw) + 127) & ~127u;

    const int tid  = threadIdx.x;
    const int lane = tid & 31;
    const int wid  = tid >> 5;
    const int wm   = wid >> 2;
    const int wn   = wid & 3;
    const int bm   = blockIdx.y * 128;
    const int bh   = blockIdx.x * 64;
    const int K    = 512;
    const int NC   = 8;

    const int ag = lane >> 3, ai = lane & 7;
    const int a_row = ai + (ag & 1) * 8;
    const int a_kb  = (ag >> 1) * 16;
    const int b_row2 = (lane & 7) + ((lane >> 4) << 3);
    const int b_kb   = ((lane >> 3) & 1) * 16;

    float acc[3][2][2][4];
#pragma unroll
    for (int g = 0; g < 3; g++)
#pragma unroll
        for (int mt = 0; mt < 2; mt++)
#pragma unroll
            for (int nt = 0; nt < 2; nt++)
#pragma unroll
                for (int j = 0; j < 4; j++) acc[g][mt][nt][j] = 0.f;

    auto load_chunk = [&](int c, int s) {
        const uint32_t sb = sbase + s * LF_STAGE;
        const int k0 = c << 6;
#pragma unroll
        for (int i = 0; i < 2; ++i) {           // A: 1024 positions
            int p = tid + i * 512;
            int row = p >> 3, cb = p & 7;
            size_t aoff = (size_t)(bm + row) * K + k0 + cb * 8;
            cp16(sb + row * TP144 + cb * 16, Ah + aoff);
        }
#pragma unroll
        for (int i = 0; i < 3; ++i) {           // B: 3 gates x 512 positions
            int p = tid + i * 512;
            int g = p >> 9, pp = p & 511;
            int row = pp >> 3, cb = pp & 7;
            size_t woff = (size_t)(g * 512 + bh + row) * 512 + k0 + cb * 8;
            cp16(sb + LF_AT + g * LF_BT + row * TP144 + cb * 16, g_Wlh + woff);
        }
        CP_COMMIT();
    };

    load_chunk(0, 0);
    load_chunk(1, 1);

    for (int c = 0; c < NC; ++c) {
        if (c + 2 < NC) load_chunk(c + 2, (c + 2) % 3);

        if (c + 2 < NC)      asm volatile("cp.async.wait_group 2;" ::: "memory");
        else if (c + 1 < NC) asm volatile("cp.async.wait_group 1;" ::: "memory");
        else                 asm volatile("cp.async.wait_group 0;" ::: "memory");
        __syncthreads();

        const uint32_t sb = sbase + (c % 3) * LF_STAGE;

#pragma unroll
        for (int ks = 0; ks < 4; ++ks) {
            const int kb = ks * 32;
            uint32_t ah[2][4];
#pragma unroll
            for (int mt = 0; mt < 2; ++mt) {
                uint32_t ro = (wm * 32 + mt * 16 + a_row) * TP144 + a_kb + kb;
                ldsm4(ah[mt], sb + ro);
            }
            uint32_t bg[3][4];
#pragma unroll
            for (int g = 0; g < 3; ++g) {
                uint32_t ro = (wn * 16 + b_row2) * TP144 + b_kb + kb;
                ldsm4(bg[g], sb + LF_AT + g * LF_BT + ro);
            }
#pragma unroll
            for (int g = 0; g < 3; ++g)
#pragma unroll
                for (int mt = 0; mt < 2; ++mt)
#pragma unroll
                    for (int nt = 0; nt < 2; ++nt)
                        mma16816(acc[g][mt][nt], ah[mt], &bg[g][nt * 2]);
        }
        __syncthreads();
    }

    const int r0 = lane >> 2;
    const int q2 = (lane & 3) * 2;
#pragma unroll
    for (int mt = 0; mt < 2; ++mt) {
#pragma unroll
        for (int nt = 0; nt < 2; ++nt) {
            int col = bh + wn * 16 + nt * 8 + q2;
            float bi0 = g_bleaf[col],        bi1 = g_bleaf[col + 1];
            float bo0 = g_bleaf[512 + col],  bo1 = g_bleaf[512 + col + 1];
            float bu0 = g_bleaf[1024 + col], bu1 = g_bleaf[1024 + col + 1];
#pragma unroll
            for (int hf = 0; hf < 2; ++hf) {
                int row = bm + wm * 32 + mt * 16 + r0 + hf * 8;
                float i0 = sigf(acc[0][mt][nt][hf * 2 + 0] + bi0);
                float i1 = sigf(acc[0][mt][nt][hf * 2 + 1] + bi1);
                float o0 = sigf(acc[1][mt][nt][hf * 2 + 0] + bo0);
                float o1 = sigf(acc[1][mt][nt][hf * 2 + 1] + bo1);
                float u0 = tanhf(acc[2][mt][nt][hf * 2 + 0] + bu0);
                float u1 = tanhf(acc[2][mt][nt][hf * 2 + 1] + bu1);
                float c0 = i0 * u0, c1 = i1 * u1;
                float h0 = o0 * tanhf(c0), h1 = o1 * tanhf(c1);
                size_t gci = (size_t)(4369 + row) * HID + col;
                size_t ghi = (size_t)row * HID + col;
                __half2 vc; vc.x = __float2half_rn(c0); vc.y = __float2half_rn(c1);
                __half2 vh; vh.x = __float2half_rn(h0); vh.y = __float2half_rn(h1);
                *(__half2*)(g_Ch + gci) = vc;
                *(__half2*)(g_Hh + ghi) = vh;
            }
        }
    }
}

// ---------------------------------------------------------------------------
// prep: pack weights (blocks [0,8192)) || convert leaf x (blocks [8192,40960))
// ---------------------------------------------------------------------------
__global__ void prep(const float* __restrict__ wi_w, const float* __restrict__ wi_b,
                     const float* __restrict__ wf_w, const float* __restrict__ wf_b,
                     const float* __restrict__ wo_w, const float* __restrict__ wo_b,
                     const float* __restrict__ wu_w, const float* __restrict__ wu_b,
                     const float* __restrict__ xleaf) {
    if (blockIdx.x < 8192) {
        int idx = blockIdx.x * 256 + threadIdx.x;
        if (idx < 2048 * 1024) {
            int r = idx >> 10, k = idx & 1023;
            float v;
            if      (r <  512) v = wi_w[r * 1024 + k];
            else if (r < 1024) v = wo_w[(r -  512) * 1024 + k];
            else if (r < 1536) v = wu_w[(r - 1024) * 1024 + k];
            else               v = (k < 512) ? wf_w[(r - 1536) * 1024 + k] : 0.f;
            g_Wnh[idx] = __float2half_rn(v);
        }
        if (idx < 1536 * 512) {
            int r = idx >> 9, k = idx & 511;
            float v;
            if      (r <  512) v = wi_w[r * 1024 + k];
            else if (r < 1024) v = wo_w[(r -  512) * 1024 + k];
            else               v = wu_w[(r - 1024) * 1024 + k];
            g_Wlh[idx] = __float2half_rn(v);
        }
        if (idx < 512 * 512) {
            int r = idx >> 9, k = idx & 511;
            g_Wfhh[idx] = __float2half_rn(wf_w[r * 1024 + 512 + k]);
        }
        if (idx < 1536)
            g_bleaf[idx] = (idx < 512) ? wi_b[idx]
                         : (idx < 1024) ? wo_b[idx - 512] : wu_b[idx - 1024];
        if (idx < 2048)
            g_bnode[idx] = (idx <  512) ? wi_b[idx]
                         : (idx < 1024) ? wo_b[idx -  512]
                         : (idx < 1536) ? wu_b[idx - 1024] : wf_b[idx - 1536];
    } else {
        int i = (blockIdx.x - 8192) * 256 + threadIdx.x;
        float4 v = ((const float4*)xleaf)[i];
        hlf hh[4];
        hh[0] = __float2half_rn(v.x); hh[1] = __float2half_rn(v.y);
        hh[2] = __float2half_rn(v.z); hh[3] = __float2half_rn(v.w);
        ((uint2*)g_Xh)[i] = *(uint2*)hh;
    }
}

// ---------------------------------------------------------------------------
// Elementwise stages
// ---------------------------------------------------------------------------
__global__ void concat_xh4(const float* __restrict__ x, int off_d, int off_c,
                           int n, int leafkids) {
    int idx = blockIdx.x * blockDim.x + threadIdx.x;
    if (idx >= n * 256) return;
    int r = idx >> 8, c4 = (idx & 255) * 4;
    float4 v;
    if (c4 < 512) {
        v = *(const float4*)(x + (size_t)(off_d + r) * IN_DIM + c4);
    } else {
        int hc = c4 - 512;
        v = make_float4(0.f, 0.f, 0.f, 0.f);
        if (leafkids) {
            size_t base = (size_t)(off_c + r * 16 - 4369) * HID + hc;
#pragma unroll
            for (int k = 0; k < 16; k++) {
                float4 t = h4_to_f4(*(const uint2*)(g_Hh + base + k * HID));
                v.x += t.x; v.y += t.y; v.z += t.z; v.w += t.w;
            }
        } else {
            size_t base = (size_t)(off_c + r * 16) * HID + hc;
#pragma unroll
            for (int k = 0; k < 16; k++) {
                float4 t = *(const float4*)(g_H + base + k * HID);
                v.x += t.x; v.y += t.y; v.z += t.z; v.w += t.w;
            }
        }
    }
    hlf hh[4];
    hh[0] = __float2half_rn(v.x); hh[1] = __float2half_rn(v.y);
    hh[2] = __float2half_rn(v.z); hh[3] = __float2half_rn(v.w);
    *(uint2*)(g_XHh + (size_t)r * 1024 + c4) = *(uint2*)hh;
}

__global__ void node_epilogue4(int off_d, int off_c, int n, int leafkids) {
    int idx = blockIdx.x * blockDim.x + threadIdx.x;
    if (idx >= n * 128) return;
    int r = idx >> 7, h4 = (idx & 127) * 4;
    const float* g = g_G + (size_t)r * 2048;
    float4 gi = *(const float4*)(g + h4);
    float4 go = *(const float4*)(g + 512 + h4);
    float4 gu = *(const float4*)(g + 1024 + h4);
    float4 gf = *(const float4*)(g + 1536 + h4);
    float a0 = sigf(gi.x) * tanhf(gu.x);
    float a1 = sigf(gi.y) * tanhf(gu.y);
    float a2 = sigf(gi.z) * tanhf(gu.z);
    float a3 = sigf(gi.w) * tanhf(gu.w);
    size_t cb = (size_t)(off_c + r * 16) * HID + h4;
#pragma unroll
    for (int k = 0; k < 16; k++) {
        float4 fh = h4_to_f4(*(const uint2*)(g_FHh + cb + k * HID));
        float4 cc;
        if (leafkids) cc = h4_to_f4(*(const uint2*)(g_Ch + cb + k * HID));
        else          cc = *(const float4*)(g_C + cb + k * HID);
        a0 += sigf(gf.x + fh.x) * cc.x;
        a1 += sigf(gf.y + fh.y) * cc.y;
        a2 += sigf(gf.z + fh.z) * cc.z;
        a3 += sigf(gf.w + fh.w) * cc.w;
    }
    size_t gidx = (size_t)(off_d + r) * HID + h4;
    *(float4*)(g_C + gidx) = make_float4(a0, a1, a2, a3);
    float4 hv = make_float4(sigf(go.x) * tanhf(a0), sigf(go.y) * tanhf(a1),
                            sigf(go.z) * tanhf(a2), sigf(go.w) * tanhf(a3));
    *(float4*)(g_H + gidx) = hv;
    hlf hh[4];
    hh[0] = __float2half_rn(a0); hh[1] = __float2half_rn(a1);
    hh[2] = __float2half_rn(a2); hh[3] = __float2half_rn(a3);
    *(uint2*)(g_Ch + gidx) = *(uint2*)hh;
}

__global__ void writeout(float* __restrict__ out) {
    int idx = blockIdx.x * blockDim.x + threadIdx.x;
    if (idx < 512)       out[idx] = g_H[idx];
    else if (idx < 1024) out[idx] = g_C[idx - 512];
}

// ---------------------------------------------------------------------------
// Launch
// ---------------------------------------------------------------------------
static void launch_gemm(const hlf* Ah, const hlf* Bh, void* Cout,
                        const float* bias, int M, int N, int K, int half_out) {
    if (M >= 1024) {
        dim3 grid(N / 128, (M + 127) / 128);
        gemm_h<<<grid, 256, GSMEM>>>(Ah, Bh, Cout, bias, M, N, K, half_out);
    } else {
        dim3 grid(N / 64, (M + 63) / 64);
        gemm_h64<<<grid, 128, G64_SMEM>>>(Ah, Bh, Cout, bias, M, N, K, half_out);
    }
}

extern "C" void kernel_launch(void* const* d_in, const int* in_sizes, int n_in,
                              void* d_out, int out_size) {
    const float* x    = (const float*)d_in[0];
    const float* wi_w = (const float*)d_in[1];
    const float* wi_b = (const float*)d_in[2];
    const float* wf_w = (const float*)d_in[3];
    const float* wf_b = (const float*)d_in[4];
    const float* wo_w = (const float*)d_in[5];
    const float* wo_b = (const float*)d_in[6];
    const float* wu_w = (const float*)d_in[7];
    const float* wu_b = (const float*)d_in[8];
    float* out = (float*)d_out;

    cudaFuncSetAttribute(gemm_h,     cudaFuncAttributeMaxDynamicSharedMemorySize, GSMEM);
    cudaFuncSetAttribute(gemm_h64,   cudaFuncAttributeMaxDynamicSharedMemorySize, G64_SMEM);
    cudaFuncSetAttribute(leaf_fused, cudaFuncAttributeMaxDynamicSharedMemorySize, LF_SMEM);

    float *pG, *pbn;
    hlf *pXh, *pCh, *pXHh, *pWnh, *pWfhh, *pFHh;
    cudaGetSymbolAddress((void**)&pG,    g_G);
    cudaGetSymbolAddress((void**)&pbn,   g_bnode);
    cudaGetSymbolAddress((void**)&pXh,   g_Xh);
    cudaGetSymbolAddress((void**)&pCh,   g_Ch);
    cudaGetSymbolAddress((void**)&pXHh,  g_XHh);
    cudaGetSymbolAddress((void**)&pWnh,  g_Wnh);
    cudaGetSymbolAddress((void**)&pWfhh, g_Wfhh);
    cudaGetSymbolAddress((void**)&pFHh,  g_FHh);

    static const int offs[6]  = {0, 1, 17, 273, 4369, 69905};
    static const int sizes[5] = {1, 16, 256, 4096, 65536};

    // 1) prep: weights -> fp16 || leaf x -> fp16
    prep<<<40960, 256>>>(wi_w, wi_b, wf_w, wf_b, wo_w, wo_b, wu_w, wu_b,
                         x + (size_t)offs[4] * IN_DIM);

    // 2) fused leaf gates (writes Ch, Hh), then FH GEMM (fp16 out)
    {
        dim3 grid(HID / 64, NLEAF / 128);
        leaf_fused<<<grid, 512, LF_SMEM>>>(pXh);
    }
    launch_gemm(pCh + (size_t)offs[4] * HID, pWfhh,
                pFHh + (size_t)offs[4] * HID, nullptr, NLEAF, 512, 512, 1);

    // 3) internal levels, bottom-up
    for (int d = 3; d >= 0; d--) {
        int n = sizes[d];
        int leafkids = (d == 3) ? 1 : 0;
        concat_xh4<<<(n * 256 + 255) / 256, 256>>>(x, offs[d], offs[d + 1], n, leafkids);
        launch_gemm(pXHh, pWnh, pG, pbn, n, 2048, 1024, 0);
        node_epilogue4<<<(n * 128 + 255) / 256, 256>>>(offs[d], offs[d + 1], n, leafkids);
        if (d > 0)
            launch_gemm(pCh + (size_t)offs[d] * HID, pWfhh,
                        pFHh + (size_t)offs[d] * HID, nullptr, n, 512, 512, 1);
    }

    // 4) output: H[0] then C[0]
    writeout<<<4, 256>>>(out);
}

// round 14
// speedup vs baseline: 1.2807x; 1.1254x over previous
#include <cuda_runtime.h>
#include <cuda_fp16.h>
#include <math.h>
#include <stdint.h>

// ---------------------------------------------------------------------------
// CSTreeLSTM on GB300: single-term fp16 HMMA GEMMs (fp32 accumulate),
// fp16 cross-kernel intermediates. BK=64 everywhere; big GEMM and leaf kernel
// both run 2 CTAs/SM for cross-CTA barrier overlap.
// Tree: 16-ary, depth 4, IN=HID=512. Levels 1,16,256,4096,65536
// (offsets 0,1,17,273,4369; total 69905).
// ---------------------------------------------------------------------------

#define IN_DIM 512
#define HID    512
#define NLEAF  65536
#define NTOT   69905

typedef __half hlf;

// ------------------------------ device scratch ------------------------------
__device__ __align__(128) float g_C [NTOT * HID];
__device__ __align__(128) float g_H [NTOT * HID];
__device__ __align__(128) hlf   g_FHh[NTOT * HID];
__device__ __align__(128) float g_G [4096 * 2048];

__device__ __align__(128) hlf g_Xh [NLEAF * IN_DIM];
__device__ __align__(128) hlf g_Ch [NTOT * HID];
__device__ __align__(128) hlf g_Hh [NLEAF * HID];
__device__ __align__(128) hlf g_XHh[4096 * 1024];

__device__ __align__(128) hlf g_Wnh[2048 * 1024];
__device__ __align__(128) hlf g_Wlh[1536 * 512];
__device__ __align__(128) hlf g_Wfhh[512 * 512];
__device__ float g_bleaf[1536];
__device__ float g_bnode[2048];

__device__ __forceinline__ float sigf(float x) { return 1.f / (1.f + expf(-x)); }

// ------------------------------ PTX helpers ---------------------------------
__device__ __forceinline__ uint32_t smem_u32(const void* p) {
    uint32_t a;
    asm("{ .reg .u64 t; cvta.to.shared.u64 t, %1; cvt.u32.u64 %0, t; }" : "=r"(a) : "l"(p));
    return a;
}

__device__ __forceinline__ void cp16(uint32_t dst, const void* src) {
    asm volatile("cp.async.cg.shared.global [%0], [%1], 16;" :: "r"(dst), "l"(src));
}
#define CP_COMMIT() asm volatile("cp.async.commit_group;" ::: "memory")

__device__ __forceinline__ void ldsm4(uint32_t* r, uint32_t addr) {
    asm volatile("ldmatrix.sync.aligned.m8n8.x4.shared.b16 {%0,%1,%2,%3}, [%4];"
                 : "=r"(r[0]), "=r"(r[1]), "=r"(r[2]), "=r"(r[3]) : "r"(addr));
}
__device__ __forceinline__ void mma16816(float* d, const uint32_t* a, const uint32_t* b) {
    asm volatile(
        "mma.sync.aligned.m16n8k16.row.col.f32.f16.f16.f32 "
        "{%0,%1,%2,%3}, {%4,%5,%6,%7}, {%8,%9}, {%0,%1,%2,%3};"
        : "+f"(d[0]), "+f"(d[1]), "+f"(d[2]), "+f"(d[3])
        : "r"(a[0]), "r"(a[1]), "r"(a[2]), "r"(a[3]), "r"(b[0]), "r"(b[1]));
}

__device__ __forceinline__ float4 h4_to_f4(uint2 u) {
    __half2 lo = *(__half2*)&u.x, hi = *(__half2*)&u.y;
    float2 a = __half22float2(lo), b = __half22float2(hi);
    return make_float4(a.x, a.y, b.x, b.y);
}

// ---------------------------------------------------------------------------
// Big GEMM: CTA 128(M) x 128(N), 256 threads / 8 warps, warp tile 32x64,
// BK=64, 3-stage cp.async, 2 CTAs/SM. N%128==0, K%64==0; M guarded.
// Row pitch 144B: conflict-free ldsm.
// ---------------------------------------------------------------------------
#define TP144 144
#define AT_B (128 * TP144)             // 18432
#define STAGE_B (2 * AT_B)             // 36864
#define GSMEM (3 * STAGE_B + 128)      // 110720

__global__ __launch_bounds__(256, 2)
void gemm_h(const hlf* __restrict__ Ah, const hlf* __restrict__ Bh,
            void* __restrict__ Cout, const float* __restrict__ bias,
            int M, int N, int K, int half_out) {
    extern __shared__ char smem_raw[];
    const uint32_t sbase = (smem_u32(smem_raw) + 127) & ~127u;

    const int tid  = threadIdx.x;
    const int lane = tid & 31;
    const int wid  = tid >> 5;
    const int wm   = wid >> 1;
    const int wn   = wid & 1;
    const int bm   = blockIdx.y * 128;
    const int bn   = blockIdx.x * 128;
    const int NC   = K >> 6;

    const int ag = lane >> 3, ai = lane & 7;
    const int a_row = ai + (ag & 1) * 8;
    const int a_kb  = (ag >> 1) * 16;
    const int b_row2 = (lane & 7) + ((lane >> 4) << 3);
    const int b_kb   = ((lane >> 3) & 1) * 16;

    float acc[2][8][4];
#pragma unroll
    for (int mt = 0; mt < 2; mt++)
#pragma unroll
        for (int nt = 0; nt < 8; nt++)
#pragma unroll
            for (int j = 0; j < 4; j++) acc[mt][nt][j] = 0.f;

    auto load_chunk = [&](int c, int s) {
        const uint32_t sb = sbase + s * STAGE_B;
        const int k0 = c << 6;
#pragma unroll
        for (int i = 0; i < 4; ++i) {
            int p = tid + i * 256;
            int row = p >> 3, cb = p & 7;
            int ar = bm + row; if (ar > M - 1) ar = M - 1;
            size_t aoff = (size_t)ar * K + k0 + cb * 8;
            size_t boff = (size_t)(bn + row) * K + k0 + cb * 8;
            uint32_t so = row * TP144 + cb * 16;
            cp16(sb + so,        Ah + aoff);
            cp16(sb + AT_B + so, Bh + boff);
        }
        CP_COMMIT();
    };

    load_chunk(0, 0);
    if (NC > 1) load_chunk(1, 1);

    for (int c = 0; c < NC; ++c) {
        if (c + 2 < NC) load_chunk(c + 2, (c + 2) % 3);

        if (c + 2 < NC)      asm volatile("cp.async.wait_group 2;" ::: "memory");
        else if (c + 1 < NC) asm volatile("cp.async.wait_group 1;" ::: "memory");
        else                 asm volatile("cp.async.wait_group 0;" ::: "memory");
        __syncthreads();

        const uint32_t sb  = sbase + (c % 3) * STAGE_B;
        const uint32_t tAh = sb, tBh = sb + AT_B;

#pragma unroll
        for (int ks = 0; ks < 4; ++ks) {
            const int kb = ks * 32;
            uint32_t ah[2][4], bh[8][2];
#pragma unroll
            for (int mt = 0; mt < 2; ++mt) {
                uint32_t ro = (wm * 32 + mt * 16 + a_row) * TP144 + a_kb + kb;
                ldsm4(ah[mt], tAh + ro);
            }
#pragma unroll
            for (int nt2 = 0; nt2 < 8; nt2 += 2) {
                uint32_t ro = (wn * 64 + nt2 * 8 + b_row2) * TP144 + b_kb + kb;
                ldsm4(&bh[nt2][0], tBh + ro);
            }
#pragma unroll
            for (int mt = 0; mt < 2; ++mt)
#pragma unroll
                for (int nt = 0; nt < 8; ++nt)
                    mma16816(acc[mt][nt], ah[mt], bh[nt]);
        }
        __syncthreads();
    }

    const int r0 = lane >> 2;
    const int q2 = (lane & 3) * 2;
#pragma unroll
    for (int mt = 0; mt < 2; ++mt) {
        int row = bm + wm * 32 + mt * 16 + r0;
#pragma unroll
        for (int nt = 0; nt < 8; ++nt) {
            int col = bn + wn * 64 + nt * 8 + q2;
            float bx = 0.f, by = 0.f;
            if (bias) { bx = bias[col]; by = bias[col + 1]; }
            float v00 = acc[mt][nt][0] + bx, v01 = acc[mt][nt][1] + by;
            float v10 = acc[mt][nt][2] + bx, v11 = acc[mt][nt][3] + by;
            if (half_out) {
                hlf* Ch = (hlf*)Cout;
                if (row < M) {
                    __half2 v; v.x = __float2half_rn(v00); v.y = __float2half_rn(v01);
                    *(__half2*)(Ch + (size_t)row * N + col) = v;
                }
                if (row + 8 < M) {
                    __half2 v; v.x = __float2half_rn(v10); v.y = __float2half_rn(v11);
                    *(__half2*)(Ch + (size_t)(row + 8) * N + col) = v;
                }
            } else {
                float* Cf = (float*)Cout;
                if (row < M)
                    *(float2*)(Cf + (size_t)row * N + col) = make_float2(v00, v01);
                if (row + 8 < M)
                    *(float2*)(Cf + (size_t)(row + 8) * N + col) = make_float2(v10, v11);
            }
        }
    }
}

// ---------------------------------------------------------------------------
// fp16 GEMM, CTA 64x64 (small M tail). 128 threads, 4 warps 32x32. BK=32.
// ---------------------------------------------------------------------------
#define TPITCH 80
#define G64_T (64 * TPITCH)
#define G64_STAGE (2 * G64_T)
#define G64_SMEM (3 * G64_STAGE + 128)

__global__ __launch_bounds__(128)
void gemm_h64(const hlf* __restrict__ Ah, const hlf* __restrict__ Bh,
              void* __restrict__ Cout, const float* __restrict__ bias,
              int M, int N, int K, int half_out) {
    extern __shared__ char smem_raw[];
    const uint32_t sbase = (smem_u32(smem_raw) + 127) & ~127u;

    const int tid  = threadIdx.x;
    const int lane = tid & 31;
    const int wid  = tid >> 5;
    const int wm   = wid >> 1;
    const int wn   = wid & 1;
    const int bm   = blockIdx.y * 64;
    const int bn   = blockIdx.x * 64;
    const int NC   = K >> 5;

    const int ag = lane >> 3, ai = lane & 7;
    const int a_row = ai + (ag & 1) * 8;
    const int a_kb  = (ag >> 1) * 16;
    const int b_row2 = (lane & 7) + ((lane >> 4) << 3);
    const int b_kb   = ((lane >> 3) & 1) * 16;

    float acc[2][4][4];
#pragma unroll
    for (int mt = 0; mt < 2; mt++)
#pragma unroll
        for (int nt = 0; nt < 4; nt++)
#pragma unroll
            for (int j = 0; j < 4; j++) acc[mt][nt][j] = 0.f;

    auto load_chunk = [&](int c, int s) {
        const uint32_t sb = sbase + s * G64_STAGE;
        const int k0 = c << 5;
#pragma unroll
        for (int it = 0; it < 2; ++it) {
            int idx = tid + it * 128;
            int row = idx >> 2, cb = idx & 3;
            int ar = bm + row; if (ar > M - 1) ar = M - 1;
            size_t aoff = (size_t)ar * K + k0 + cb * 8;
            size_t boff = (size_t)(bn + row) * K + k0 + cb * 8;
            uint32_t so = row * TPITCH + cb * 16;
            cp16(sb + so,         Ah + aoff);
            cp16(sb + G64_T + so, Bh + boff);
        }
        CP_COMMIT();
    };

    load_chunk(0, 0);
    if (NC > 1) load_chunk(1, 1);

    for (int c = 0; c < NC; ++c) {
        if (c + 2 < NC) load_chunk(c + 2, (c + 2) % 3);

        if (c + 2 < NC)      asm volatile("cp.async.wait_group 2;" ::: "memory");
        else if (c + 1 < NC) asm volatile("cp.async.wait_group 1;" ::: "memory");
        else                 asm volatile("cp.async.wait_group 0;" ::: "memory");
        __syncthreads();

        const uint32_t sb  = sbase + (c % 3) * G64_STAGE;
        const uint32_t tAh = sb, tBh = sb + G64_T;

#pragma unroll
        for (int ks = 0; ks < 2; ++ks) {
            const int kb = ks * 32;
            uint32_t ah[2][4], bh[4][2];
#pragma unroll
            for (int mt = 0; mt < 2; ++mt) {
                uint32_t ro = (wm * 32 + mt * 16 + a_row) * TPITCH + a_kb + kb;
                ldsm4(ah[mt], tAh + ro);
            }
#pragma unroll
            for (int nt2 = 0; nt2 < 4; nt2 += 2) {
                uint32_t ro = (wn * 32 + nt2 * 8 + b_row2) * TPITCH + b_kb + kb;
                ldsm4(&bh[nt2][0], tBh + ro);
            }
#pragma unroll
            for (int mt = 0; mt < 2; ++mt)
#pragma unroll
                for (int nt = 0; nt < 4; ++nt)
                    mma16816(acc[mt][nt], ah[mt], bh[nt]);
        }
        __syncthreads();
    }

    const int r0 = lane >> 2;
    const int q2 = (lane & 3) * 2;
#pragma unroll
    for (int mt = 0; mt < 2; ++mt) {
        int row = bm + wm * 32 + mt * 16 + r0;
#pragma unroll
        for (int nt = 0; nt < 4; ++nt) {
            int col = bn + wn * 32 + nt * 8 + q2;
            float bx = 0.f, by = 0.f;
            if (bias) { bx = bias[col]; by = bias[col + 1]; }
            float v00 = acc[mt][nt][0] + bx, v01 = acc[mt][nt][1] + by;
            float v10 = acc[mt][nt][2] + bx, v11 = acc[mt][nt][3] + by;
            if (half_out) {
                hlf* Ch = (hlf*)Cout;
                if (row < M) {
                    __half2 v; v.x = __float2half_rn(v00); v.y = __float2half_rn(v01);
                    *(__half2*)(Ch + (size_t)row * N + col) = v;
                }
                if (row + 8 < M) {
                    __half2 v; v.x = __float2half_rn(v10); v.y = __float2half_rn(v11);
                    *(__half2*)(Ch + (size_t)(row + 8) * N + col) = v;
                }
            } else {
                float* Cf = (float*)Cout;
                if (row < M)
                    *(float2*)(Cf + (size_t)row * N + col) = make_float2(v00, v01);
                if (row + 8 < M)
                    *(float2*)(Cf + (size_t)(row + 8) * N + col) = make_float2(v10, v11);
            }
        }
    }
}

// ---------------------------------------------------------------------------
// Fused leaf kernel. CTA 64(M) x 64(h) x 3 gates, 256 threads / 8 warps,
// warp layout 2(M)x4(h), warp tile 32x16 per gate, BK=64, 3 stages,
// 2 CTAs/SM. Writes Ch, Hh (fp16). K=512.
// ---------------------------------------------------------------------------
#define LF_AT (64 * TP144)              // 9216
#define LF_BT (64 * TP144)              // 9216
#define LF_STAGE (LF_AT + 3 * LF_BT)    // 36864
#define LF_SMEM (3 * LF_STAGE + 128)    // 110720

__global__ __launch_bounds__(256, 2)
void leaf_fused(const hlf* __restrict__ Ah) {
    extern __shared__ char smem_raw[];
    const uint32_t sbase = (smem_u32(smem_raw) + 127) & ~127u;

    const int tid  = threadIdx.x;
    const int lane = tid & 31;
    const int wid  = tid >> 5;          // 0..7
    const int wm   = wid >> 2;          // 0..1 (M slices of 32)
    const int wn   = wid & 3;           // 0..3 (h slices of 16)
    const int bm   = blockIdx.y * 64;
    const int bh   = blockIdx.x * 64;
    const int K    = 512;
    const int NC   = 8;

    const int ag = lane >> 3, ai = lane & 7;
    const int a_row = ai + (ag & 1) * 8;
    const int a_kb  = (ag >> 1) * 16;
    const int b_row2 = (lane & 7) + ((lane >> 4) << 3);
    const int b_kb   = ((lane >> 3) & 1) * 16;

    float acc[3][2][2][4];
#pragma unroll
    for (int g = 0; g < 3; g++)
#pragma unroll
        for (int mt = 0; mt < 2; mt++)
#pragma unroll
            for (int nt = 0; nt < 2; nt++)
#pragma unroll
                for (int j = 0; j < 4; j++) acc[g][mt][nt][j] = 0.f;

    auto load_chunk = [&](int c, int s) {
        const uint32_t sb = sbase + s * LF_STAGE;
        const int k0 = c << 6;
#pragma unroll
        for (int i = 0; i < 2; ++i) {           // A: 64 rows x 8 chunks = 512
            int p = tid + i * 256;
            int row = p >> 3, cb = p & 7;
            size_t aoff = (size_t)(bm + row) * K + k0 + cb * 8;
            cp16(sb + row * TP144 + cb * 16, Ah + aoff);
        }
#pragma unroll
        for (int i = 0; i < 6; ++i) {           // B: 3 gates x 512 = 1536
            int p = tid + i * 256;
            int g = p >> 9, pp = p & 511;
            int row = pp >> 3, cb = pp & 7;
            size_t woff = (size_t)(g * 512 + bh + row) * 512 + k0 + cb * 8;
            cp16(sb + LF_AT + g * LF_BT + row * TP144 + cb * 16, g_Wlh + woff);
        }
        CP_COMMIT();
    };

    load_chunk(0, 0);
    load_chunk(1, 1);

    for (int c = 0; c < NC; ++c) {
        if (c + 2 < NC) load_chunk(c + 2, (c + 2) % 3);

        if (c + 2 < NC)      asm volatile("cp.async.wait_group 2;" ::: "memory");
        else if (c + 1 < NC) asm volatile("cp.async.wait_group 1;" ::: "memory");
        else                 asm volatile("cp.async.wait_group 0;" ::: "memory");
        __syncthreads();

        const uint32_t sb = sbase + (c % 3) * LF_STAGE;

#pragma unroll
        for (int ks = 0; ks < 4; ++ks) {
            const int kb = ks * 32;
            uint32_t ah[2][4];
#pragma unroll
            for (int mt = 0; mt < 2; ++mt) {
                uint32_t ro = (wm * 32 + mt * 16 + a_row) * TP144 + a_kb + kb;
                ldsm4(ah[mt], sb + ro);
            }
            uint32_t bg[3][4];
#pragma unroll
            for (int g = 0; g < 3; ++g) {
                uint32_t ro = (wn * 16 + b_row2) * TP144 + b_kb + kb;
                ldsm4(bg[g], sb + LF_AT + g * LF_BT + ro);
            }
#pragma unroll
            for (int g = 0; g < 3; ++g)
#pragma unroll
                for (int mt = 0; mt < 2; ++mt)
#pragma unroll
                    for (int nt = 0; nt < 2; ++nt)
                        mma16816(acc[g][mt][nt], ah[mt], &bg[g][nt * 2]);
        }
        __syncthreads();
    }

    const int r0 = lane >> 2;
    const int q2 = (lane & 3) * 2;
#pragma unroll
    for (int mt = 0; mt < 2; ++mt) {
#pragma unroll
        for (int nt = 0; nt < 2; ++nt) {
            int col = bh + wn * 16 + nt * 8 + q2;
            float bi0 = g_bleaf[col],        bi1 = g_bleaf[col + 1];
            float bo0 = g_bleaf[512 + col],  bo1 = g_bleaf[512 + col + 1];
            float bu0 = g_bleaf[1024 + col], bu1 = g_bleaf[1024 + col + 1];
#pragma unroll
            for (int hf = 0; hf < 2; ++hf) {
                int row = bm + wm * 32 + mt * 16 + r0 + hf * 8;
                float i0 = sigf(acc[0][mt][nt][hf * 2 + 0] + bi0);
                float i1 = sigf(acc[0][mt][nt][hf * 2 + 1] + bi1);
                float o0 = sigf(acc[1][mt][nt][hf * 2 + 0] + bo0);
                float o1 = sigf(acc[1][mt][nt][hf * 2 + 1] + bo1);
                float u0 = tanhf(acc[2][mt][nt][hf * 2 + 0] + bu0);
                float u1 = tanhf(acc[2][mt][nt][hf * 2 + 1] + bu1);
                float c0 = i0 * u0, c1 = i1 * u1;
                float h0 = o0 * tanhf(c0), h1 = o1 * tanhf(c1);
                size_t gci = (size_t)(4369 + row) * HID + col;
                size_t ghi = (size_t)row * HID + col;
                __half2 vc; vc.x = __float2half_rn(c0); vc.y = __float2half_rn(c1);
                __half2 vh; vh.x = __float2half_rn(h0); vh.y = __float2half_rn(h1);
                *(__half2*)(g_Ch + gci) = vc;
                *(__half2*)(g_Hh + ghi) = vh;
            }
        }
    }
}

// ---------------------------------------------------------------------------
// prep: pack weights (blocks [0,8192)) || convert leaf x (blocks [8192,40960))
// ---------------------------------------------------------------------------
__global__ void prep(const float* __restrict__ wi_w, const float* __restrict__ wi_b,
                     const float* __restrict__ wf_w, const float* __restrict__ wf_b,
                     const float* __restrict__ wo_w, const float* __restrict__ wo_b,
                     const float* __restrict__ wu_w, const float* __restrict__ wu_b,
                     const float* __restrict__ xleaf) {
    if (blockIdx.x < 8192) {
        int idx = blockIdx.x * 256 + threadIdx.x;
        if (idx < 2048 * 1024) {
            int r = idx >> 10, k = idx & 1023;
            float v;
            if      (r <  512) v = wi_w[r * 1024 + k];
            else if (r < 1024) v = wo_w[(r -  512) * 1024 + k];
            else if (r < 1536) v = wu_w[(r - 1024) * 1024 + k];
            else               v = (k < 512) ? wf_w[(r - 1536) * 1024 + k] : 0.f;
            g_Wnh[idx] = __float2half_rn(v);
        }
        if (idx < 1536 * 512) {
            int r = idx >> 9, k = idx & 511;
            float v;
            if      (r <  512) v = wi_w[r * 1024 + k];
            else if (r < 1024) v = wo_w[(r -  512) * 1024 + k];
            else               v = wu_w[(r - 1024) * 1024 + k];
            g_Wlh[idx] = __float2half_rn(v);
        }
        if (idx < 512 * 512) {
            int r = idx >> 9, k = idx & 511;
            g_Wfhh[idx] = __float2half_rn(wf_w[r * 1024 + 512 + k]);
        }
        if (idx < 1536)
            g_bleaf[idx] = (idx < 512) ? wi_b[idx]
                         : (idx < 1024) ? wo_b[idx - 512] : wu_b[idx - 1024];
        if (idx < 2048)
            g_bnode[idx] = (idx <  512) ? wi_b[idx]
                         : (idx < 1024) ? wo_b[idx -  512]
                         : (idx < 1536) ? wu_b[idx - 1024] : wf_b[idx - 1536];
    } else {
        int i = (blockIdx.x - 8192) * 256 + threadIdx.x;
        float4 v = ((const float4*)xleaf)[i];
        hlf hh[4];
        hh[0] = __float2half_rn(v.x); hh[1] = __float2half_rn(v.y);
        hh[2] = __float2half_rn(v.z); hh[3] = __float2half_rn(v.w);
        ((uint2*)g_Xh)[i] = *(uint2*)hh;
    }
}

// ---------------------------------------------------------------------------
// Elementwise stages
// ---------------------------------------------------------------------------
__global__ void concat_xh4(const float* __restrict__ x, int off_d, int off_c,
                           int n, int leafkids) {
    int idx = blockIdx.x * blockDim.x + threadIdx.x;
    if (idx >= n * 256) return;
    int r = idx >> 8, c4 = (idx & 255) * 4;
    float4 v;
    if (c4 < 512) {
        v = *(const float4*)(x + (size_t)(off_d + r) * IN_DIM + c4);
    } else {
        int hc = c4 - 512;
        v = make_float4(0.f, 0.f, 0.f, 0.f);
        if (leafkids) {
            size_t base = (size_t)(off_c + r * 16 - 4369) * HID + hc;
#pragma unroll
            for (int k = 0; k < 16; k++) {
                float4 t = h4_to_f4(*(const uint2*)(g_Hh + base + k * HID));
                v.x += t.x; v.y += t.y; v.z += t.z; v.w += t.w;
            }
        } else {
            size_t base = (size_t)(off_c + r * 16) * HID + hc;
#pragma unroll
            for (int k = 0; k < 16; k++) {
                float4 t = *(const float4*)(g_H + base + k * HID);
                v.x += t.x; v.y += t.y; v.z += t.z; v.w += t.w;
            }
        }
    }
    hlf hh[4];
    hh[0] = __float2half_rn(v.x); hh[1] = __float2half_rn(v.y);
    hh[2] = __float2half_rn(v.z); hh[3] = __float2half_rn(v.w);
    *(uint2*)(g_XHh + (size_t)r * 1024 + c4) = *(uint2*)hh;
}

__global__ void node_epilogue4(int off_d, int off_c, int n, int leafkids) {
    int idx = blockIdx.x * blockDim.x + threadIdx.x;
    if (idx >= n * 128) return;
    int r = idx >> 7, h4 = (idx & 127) * 4;
    const float* g = g_G + (size_t)r * 2048;
    float4 gi = *(const float4*)(g + h4);
    float4 go = *(const float4*)(g + 512 + h4);
    float4 gu = *(const float4*)(g + 1024 + h4);
    float4 gf = *(const float4*)(g + 1536 + h4);
    float a0 = sigf(gi.x) * tanhf(gu.x);
    float a1 = sigf(gi.y) * tanhf(gu.y);
    float a2 = sigf(gi.z) * tanhf(gu.z);
    float a3 = sigf(gi.w) * tanhf(gu.w);
    size_t cb = (size_t)(off_c + r * 16) * HID + h4;
#pragma unroll
    for (int k = 0; k < 16; k++) {
        float4 fh = h4_to_f4(*(const uint2*)(g_FHh + cb + k * HID));
        float4 cc;
        if (leafkids) cc = h4_to_f4(*(const uint2*)(g_Ch + cb + k * HID));
        else          cc = *(const float4*)(g_C + cb + k * HID);
        a0 += sigf(gf.x + fh.x) * cc.x;
        a1 += sigf(gf.y + fh.y) * cc.y;
        a2 += sigf(gf.z + fh.z) * cc.z;
        a3 += sigf(gf.w + fh.w) * cc.w;
    }
    size_t gidx = (size_t)(off_d + r) * HID + h4;
    *(float4*)(g_C + gidx) = make_float4(a0, a1, a2, a3);
    float4 hv = make_float4(sigf(go.x) * tanhf(a0), sigf(go.y) * tanhf(a1),
                            sigf(go.z) * tanhf(a2), sigf(go.w) * tanhf(a3));
    *(float4*)(g_H + gidx) = hv;
    hlf hh[4];
    hh[0] = __float2half_rn(a0); hh[1] = __float2half_rn(a1);
    hh[2] = __float2half_rn(a2); hh[3] = __float2half_rn(a3);
    *(uint2*)(g_Ch + gidx) = *(uint2*)hh;
}

__global__ void writeout(float* __restrict__ out) {
    int idx = blockIdx.x * blockDim.x + threadIdx.x;
    if (idx < 512)       out[idx] = g_H[idx];
    else if (idx < 1024) out[idx] = g_C[idx - 512];
}

// ---------------------------------------------------------------------------
// Launch
// ---------------------------------------------------------------------------
static void launch_gemm(const hlf* Ah, const hlf* Bh, void* Cout,
                        const float* bias, int M, int N, int K, int half_out) {
    if (M >= 1024) {
        dim3 grid(N / 128, (M + 127) / 128);
        gemm_h<<<grid, 256, GSMEM>>>(Ah, Bh, Cout, bias, M, N, K, half_out);
    } else {
        dim3 grid(N / 64, (M + 63) / 64);
        gemm_h64<<<grid, 128, G64_SMEM>>>(Ah, Bh, Cout, bias, M, N, K, half_out);
    }
}

extern "C" void kernel_launch(void* const* d_in, const int* in_sizes, int n_in,
                              void* d_out, int out_size) {
    const float* x    = (const float*)d_in[0];
    const float* wi_w = (const float*)d_in[1];
    const float* wi_b = (const float*)d_in[2];
    const float* wf_w = (const float*)d_in[3];
    const float* wf_b = (const float*)d_in[4];
    const float* wo_w = (const float*)d_in[5];
    const float* wo_b = (const float*)d_in[6];
    const float* wu_w = (const float*)d_in[7];
    const float* wu_b = (const float*)d_in[8];
    float* out = (float*)d_out;

    cudaFuncSetAttribute(gemm_h,     cudaFuncAttributeMaxDynamicSharedMemorySize, GSMEM);
    cudaFuncSetAttribute(gemm_h64,   cudaFuncAttributeMaxDynamicSharedMemorySize, G64_SMEM);
    cudaFuncSetAttribute(leaf_fused, cudaFuncAttributeMaxDynamicSharedMemorySize, LF_SMEM);

    float *pG, *pbn;
    hlf *pXh, *pCh, *pXHh, *pWnh, *pWfhh, *pFHh;
    cudaGetSymbolAddress((void**)&pG,    g_G);
    cudaGetSymbolAddress((void**)&pbn,   g_bnode);
    cudaGetSymbolAddress((void**)&pXh,   g_Xh);
    cudaGetSymbolAddress((void**)&pCh,   g_Ch);
    cudaGetSymbolAddress((void**)&pXHh,  g_XHh);
    cudaGetSymbolAddress((void**)&pWnh,  g_Wnh);
    cudaGetSymbolAddress((void**)&pWfhh, g_Wfhh);
    cudaGetSymbolAddress((void**)&pFHh,  g_FHh);

    static const int offs[6]  = {0, 1, 17, 273, 4369, 69905};
    static const int sizes[5] = {1, 16, 256, 4096, 65536};

    // 1) prep: weights -> fp16 || leaf x -> fp16
    prep<<<40960, 256>>>(wi_w, wi_b, wf_w, wf_b, wo_w, wo_b, wu_w, wu_b,
                         x + (size_t)offs[4] * IN_DIM);

    // 2) fused leaf gates (writes Ch, Hh), then FH GEMM (fp16 out)
    {
        dim3 grid(HID / 64, NLEAF / 64);
        leaf_fused<<<grid, 256, LF_SMEM>>>(pXh);
    }
    launch_gemm(pCh + (size_t)offs[4] * HID, pWfhh,
                pFHh + (size_t)offs[4] * HID, nullptr, NLEAF, 512, 512, 1);

    // 3) internal levels, bottom-up
    for (int d = 3; d >= 0; d--) {
        int n = sizes[d];
        int leafkids = (d == 3) ? 1 : 0;
        concat_xh4<<<(n * 256 + 255) / 256, 256>>>(x, offs[d], offs[d + 1], n, leafkids);
        launch_gemm(pXHh, pWnh, pG, pbn, n, 2048, 1024, 0);
        node_epilogue4<<<(n * 128 + 255) / 256, 256>>>(offs[d], offs[d + 1], n, leafkids);
        if (d > 0)
            launch_gemm(pCh + (size_t)offs[d] * HID, pWfhh,
                        pFHh + (size_t)offs[d] * HID, nullptr, n, 512, 512, 1);
    }

    // 4) output: H[0] then C[0]
    writeout<<<4, 256>>>(out);
}

// round 15
// speedup vs baseline: 1.3217x; 1.0320x over previous
#include <cuda_runtime.h>
#include <cuda_fp16.h>
#include <math.h>
#include <stdint.h>

// ---------------------------------------------------------------------------
// CSTreeLSTM on GB300: single-term fp16 HMMA GEMMs (fp32 accumulate),
// fp16 intermediates, BK=64, 2 CTAs/SM on hot kernels. leaf_fused folds the
// 16-way sibling H-sum into its epilogue (writes XHh h-part directly).
// Tree: 16-ary, depth 4, IN=HID=512. Levels 1,16,256,4096,65536
// (offsets 0,1,17,273,4369; total 69905).
// ---------------------------------------------------------------------------

#define IN_DIM 512
#define HID    512
#define NLEAF  65536
#define NTOT   69905

typedef __half hlf;

// ------------------------------ device scratch ------------------------------
__device__ __align__(128) float g_C [NTOT * HID];
__device__ __align__(128) float g_H [NTOT * HID];
__device__ __align__(128) hlf   g_FHh[NTOT * HID];
__device__ __align__(128) float g_G [4096 * 2048];

__device__ __align__(128) hlf g_Xh [NLEAF * IN_DIM];
__device__ __align__(128) hlf g_Ch [NTOT * HID];
__device__ __align__(128) hlf g_XHh[4096 * 1024];

__device__ __align__(128) hlf g_Wnh[2048 * 1024];
__device__ __align__(128) hlf g_Wlh[1536 * 512];
__device__ __align__(128) hlf g_Wfhh[512 * 512];
__device__ float g_bleaf[1536];
__device__ float g_bnode[2048];

__device__ __forceinline__ float sigf(float x) { return 1.f / (1.f + expf(-x)); }

// ------------------------------ PTX helpers ---------------------------------
__device__ __forceinline__ uint32_t smem_u32(const void* p) {
    uint32_t a;
    asm("{ .reg .u64 t; cvta.to.shared.u64 t, %1; cvt.u32.u64 %0, t; }" : "=r"(a) : "l"(p));
    return a;
}

__device__ __forceinline__ void cp16(uint32_t dst, const void* src) {
    asm volatile("cp.async.cg.shared.global [%0], [%1], 16;" :: "r"(dst), "l"(src));
}
#define CP_COMMIT() asm volatile("cp.async.commit_group;" ::: "memory")

__device__ __forceinline__ void ldsm4(uint32_t* r, uint32_t addr) {
    asm volatile("ldmatrix.sync.aligned.m8n8.x4.shared.b16 {%0,%1,%2,%3}, [%4];"
                 : "=r"(r[0]), "=r"(r[1]), "=r"(r[2]), "=r"(r[3]) : "r"(addr));
}
__device__ __forceinline__ void mma16816(float* d, const uint32_t* a, const uint32_t* b) {
    asm volatile(
        "mma.sync.aligned.m16n8k16.row.col.f32.f16.f16.f32 "
        "{%0,%1,%2,%3}, {%4,%5,%6,%7}, {%8,%9}, {%0,%1,%2,%3};"
        : "+f"(d[0]), "+f"(d[1]), "+f"(d[2]), "+f"(d[3])
        : "r"(a[0]), "r"(a[1]), "r"(a[2]), "r"(a[3]), "r"(b[0]), "r"(b[1]));
}

__device__ __forceinline__ float4 h4_to_f4(uint2 u) {
    __half2 lo = *(__half2*)&u.x, hi = *(__half2*)&u.y;
    float2 a = __half22float2(lo), b = __half22float2(hi);
    return make_float4(a.x, a.y, b.x, b.y);
}

// ---------------------------------------------------------------------------
// Big GEMM: CTA 128(M) x 128(N), 256 threads / 8 warps, warp tile 32x64,
// BK=64, 3-stage cp.async, 2 CTAs/SM. N%128==0, K%64==0; M guarded.
// ---------------------------------------------------------------------------
#define TP144 144
#define AT_B (128 * TP144)
#define STAGE_B (2 * AT_B)
#define GSMEM (3 * STAGE_B + 128)

__global__ __launch_bounds__(256, 2)
void gemm_h(const hlf* __restrict__ Ah, const hlf* __restrict__ Bh,
            void* __restrict__ Cout, const float* __restrict__ bias,
            int M, int N, int K, int half_out) {
    extern __shared__ char smem_raw[];
    const uint32_t sbase = (smem_u32(smem_raw) + 127) & ~127u;

    const int tid  = threadIdx.x;
    const int lane = tid & 31;
    const int wid  = tid >> 5;
    const int wm   = wid >> 1;
    const int wn   = wid & 1;
    const int bm   = blockIdx.y * 128;
    const int bn   = blockIdx.x * 128;
    const int NC   = K >> 6;

    const int ag = lane >> 3, ai = lane & 7;
    const int a_row = ai + (ag & 1) * 8;
    const int a_kb  = (ag >> 1) * 16;
    const int b_row2 = (lane & 7) + ((lane >> 4) << 3);
    const int b_kb   = ((lane >> 3) & 1) * 16;

    float acc[2][8][4];
#pragma unroll
    for (int mt = 0; mt < 2; mt++)
#pragma unroll
        for (int nt = 0; nt < 8; nt++)
#pragma unroll
            for (int j = 0; j < 4; j++) acc[mt][nt][j] = 0.f;

    auto load_chunk = [&](int c, int s) {
        const uint32_t sb = sbase + s * STAGE_B;
        const int k0 = c << 6;
#pragma unroll
        for (int i = 0; i < 4; ++i) {
            int p = tid + i * 256;
            int row = p >> 3, cb = p & 7;
            int ar = bm + row; if (ar > M - 1) ar = M - 1;
            size_t aoff = (size_t)ar * K + k0 + cb * 8;
            size_t boff = (size_t)(bn + row) * K + k0 + cb * 8;
            uint32_t so = row * TP144 + cb * 16;
            cp16(sb + so,        Ah + aoff);
            cp16(sb + AT_B + so, Bh + boff);
        }
        CP_COMMIT();
    };

    load_chunk(0, 0);
    if (NC > 1) load_chunk(1, 1);

    for (int c = 0; c < NC; ++c) {
        if (c + 2 < NC) load_chunk(c + 2, (c + 2) % 3);

        if (c + 2 < NC)      asm volatile("cp.async.wait_group 2;" ::: "memory");
        else if (c + 1 < NC) asm volatile("cp.async.wait_group 1;" ::: "memory");
        else                 asm volatile("cp.async.wait_group 0;" ::: "memory");
        __syncthreads();

        const uint32_t sb  = sbase + (c % 3) * STAGE_B;
        const uint32_t tAh = sb, tBh = sb + AT_B;

#pragma unroll
        for (int ks = 0; ks < 4; ++ks) {
            const int kb = ks * 32;
            uint32_t ah[2][4], bh[8][2];
#pragma unroll
            for (int mt = 0; mt < 2; ++mt) {
                uint32_t ro = (wm * 32 + mt * 16 + a_row) * TP144 + a_kb + kb;
                ldsm4(ah[mt], tAh + ro);
            }
#pragma unroll
            for (int nt2 = 0; nt2 < 8; nt2 += 2) {
                uint32_t ro = (wn * 64 + nt2 * 8 + b_row2) * TP144 + b_kb + kb;
                ldsm4(&bh[nt2][0], tBh + ro);
            }
#pragma unroll
            for (int mt = 0; mt < 2; ++mt)
#pragma unroll
                for (int nt = 0; nt < 8; ++nt)
                    mma16816(acc[mt][nt], ah[mt], bh[nt]);
        }
        __syncthreads();
    }

    const int r0 = lane >> 2;
    const int q2 = (lane & 3) * 2;
#pragma unroll
    for (int mt = 0; mt < 2; ++mt) {
        int row = bm + wm * 32 + mt * 16 + r0;
#pragma unroll
        for (int nt = 0; nt < 8; ++nt) {
            int col = bn + wn * 64 + nt * 8 + q2;
            float bx = 0.f, by = 0.f;
            if (bias) { bx = bias[col]; by = bias[col + 1]; }
            float v00 = acc[mt][nt][0] + bx, v01 = acc[mt][nt][1] + by;
            float v10 = acc[mt][nt][2] + bx, v11 = acc[mt][nt][3] + by;
            if (half_out) {
                hlf* Ch = (hlf*)Cout;
                if (row < M) {
                    __half2 v; v.x = __float2half_rn(v00); v.y = __float2half_rn(v01);
                    *(__half2*)(Ch + (size_t)row * N + col) = v;
                }
                if (row + 8 < M) {
                    __half2 v; v.x = __float2half_rn(v10); v.y = __float2half_rn(v11);
                    *(__half2*)(Ch + (size_t)(row + 8) * N + col) = v;
                }
            } else {
                float* Cf = (float*)Cout;
                if (row < M)
                    *(float2*)(Cf + (size_t)row * N + col) = make_float2(v00, v01);
                if (row + 8 < M)
                    *(float2*)(Cf + (size_t)(row + 8) * N + col) = make_float2(v10, v11);
            }
        }
    }
}

// ---------------------------------------------------------------------------
// fp16 GEMM, CTA 64x64 (small M tail). 128 threads, 4 warps 32x32. BK=32.
// ---------------------------------------------------------------------------
#define TPITCH 80
#define G64_T (64 * TPITCH)
#define G64_STAGE (2 * G64_T)
#define G64_SMEM (3 * G64_STAGE + 128)

__global__ __launch_bounds__(128)
void gemm_h64(const hlf* __restrict__ Ah, const hlf* __restrict__ Bh,
              void* __restrict__ Cout, const float* __restrict__ bias,
              int M, int N, int K, int half_out) {
    extern __shared__ char smem_raw[];
    const uint32_t sbase = (smem_u32(smem_raw) + 127) & ~127u;

    const int tid  = threadIdx.x;
    const int lane = tid & 31;
    const int wid  = tid >> 5;
    const int wm   = wid >> 1;
    const int wn   = wid & 1;
    const int bm   = blockIdx.y * 64;
    const int bn   = blockIdx.x * 64;
    const int NC   = K >> 5;

    const int ag = lane >> 3, ai = lane & 7;
    const int a_row = ai + (ag & 1) * 8;
    const int a_kb  = (ag >> 1) * 16;
    const int b_row2 = (lane & 7) + ((lane >> 4) << 3);
    const int b_kb   = ((lane >> 3) & 1) * 16;

    float acc[2][4][4];
#pragma unroll
    for (int mt = 0; mt < 2; mt++)
#pragma unroll
        for (int nt = 0; nt < 4; nt++)
#pragma unroll
            for (int j = 0; j < 4; j++) acc[mt][nt][j] = 0.f;

    auto load_chunk = [&](int c, int s) {
        const uint32_t sb = sbase + s * G64_STAGE;
        const int k0 = c << 5;
#pragma unroll
        for (int it = 0; it < 2; ++it) {
            int idx = tid + it * 128;
            int row = idx >> 2, cb = idx & 3;
            int ar = bm + row; if (ar > M - 1) ar = M - 1;
            size_t aoff = (size_t)ar * K + k0 + cb * 8;
            size_t boff = (size_t)(bn + row) * K + k0 + cb * 8;
            uint32_t so = row * TPITCH + cb * 16;
            cp16(sb + so,         Ah + aoff);
            cp16(sb + G64_T + so, Bh + boff);
        }
        CP_COMMIT();
    };

    load_chunk(0, 0);
    if (NC > 1) load_chunk(1, 1);

    for (int c = 0; c < NC; ++c) {
        if (c + 2 < NC) load_chunk(c + 2, (c + 2) % 3);

        if (c + 2 < NC)      asm volatile("cp.async.wait_group 2;" ::: "memory");
        else if (c + 1 < NC) asm volatile("cp.async.wait_group 1;" ::: "memory");
        else                 asm volatile("cp.async.wait_group 0;" ::: "memory");
        __syncthreads();

        const uint32_t sb  = sbase + (c % 3) * G64_STAGE;
        const uint32_t tAh = sb, tBh = sb + G64_T;

#pragma unroll
        for (int ks = 0; ks < 2; ++ks) {
            const int kb = ks * 32;
            uint32_t ah[2][4], bh[4][2];
#pragma unroll
            for (int mt = 0; mt < 2; ++mt) {
                uint32_t ro = (wm * 32 + mt * 16 + a_row) * TPITCH + a_kb + kb;
                ldsm4(ah[mt], tAh + ro);
            }
#pragma unroll
            for (int nt2 = 0; nt2 < 4; nt2 += 2) {
                uint32_t ro = (wn * 32 + nt2 * 8 + b_row2) * TPITCH + b_kb + kb;
                ldsm4(&bh[nt2][0], tBh + ro);
            }
#pragma unroll
            for (int mt = 0; mt < 2; ++mt)
#pragma unroll
                for (int nt = 0; nt < 4; ++nt)
                    mma16816(acc[mt][nt], ah[mt], bh[nt]);
        }
        __syncthreads();
    }

    const int r0 = lane >> 2;
    const int q2 = (lane & 3) * 2;
#pragma unroll
    for (int mt = 0; mt < 2; ++mt) {
        int row = bm + wm * 32 + mt * 16 + r0;
#pragma unroll
        for (int nt = 0; nt < 4; ++nt) {
            int col = bn + wn * 32 + nt * 8 + q2;
            float bx = 0.f, by = 0.f;
            if (bias) { bx = bias[col]; by = bias[col + 1]; }
            float v00 = acc[mt][nt][0] + bx, v01 = acc[mt][nt][1] + by;
            float v10 = acc[mt][nt][2] + bx, v11 = acc[mt][nt][3] + by;
            if (half_out) {
                hlf* Ch = (hlf*)Cout;
                if (row < M) {
                    __half2 v; v.x = __float2half_rn(v00); v.y = __float2half_rn(v01);
                    *(__half2*)(Ch + (size_t)row * N + col) = v;
                }
                if (row + 8 < M) {
                    __half2 v; v.x = __float2half_rn(v10); v.y = __float2half_rn(v11);
                    *(__half2*)(Ch + (size_t)(row + 8) * N + col) = v;
                }
            } else {
                float* Cf = (float*)Cout;
                if (row < M)
                    *(float2*)(Cf + (size_t)row * N + col) = make_float2(v00, v01);
                if (row + 8 < M)
                    *(float2*)(Cf + (size_t)(row + 8) * N + col) = make_float2(v10, v11);
            }
        }
    }
}

// ---------------------------------------------------------------------------
// Fused leaf kernel. CTA 64(M) x 64(h) x 3 gates, 256 threads / 8 warps,
// warp layout 2(M)x4(h), warp tile 32x16/gate, BK=64, 3 stages, 2 CTAs/SM.
// Epilogue: writes Ch (fp16) AND the 16-way sibling h-sum directly into
// XHh[group][512+col] (fp16). No separate H buffer.
// Row block of warp (32 rows) = 2 sibling groups (mt). Group rows split over
// lane bits r0 (mask 4,8,16) and hf: butterfly + local add reduces fully.
// ---------------------------------------------------------------------------
#define LF_AT (64 * TP144)
#define LF_BT (64 * TP144)
#define LF_STAGE (LF_AT + 3 * LF_BT)
#define LF_SMEM (3 * LF_STAGE + 128)

__global__ __launch_bounds__(256, 2)
void leaf_fused(const hlf* __restrict__ Ah) {
    extern __shared__ char smem_raw[];
    const uint32_t sbase = (smem_u32(smem_raw) + 127) & ~127u;

    const int tid  = threadIdx.x;
    const int lane = tid & 31;
    const int wid  = tid >> 5;
    const int wm   = wid >> 2;
    const int wn   = wid & 3;
    const int bm   = blockIdx.y * 64;
    const int bh   = blockIdx.x * 64;
    const int K    = 512;
    const int NC   = 8;

    const int ag = lane >> 3, ai = lane & 7;
    const int a_row = ai + (ag & 1) * 8;
    const int a_kb  = (ag >> 1) * 16;
    const int b_row2 = (lane & 7) + ((lane >> 4) << 3);
    const int b_kb   = ((lane >> 3) & 1) * 16;

    float acc[3][2][2][4];
#pragma unroll
    for (int g = 0; g < 3; g++)
#pragma unroll
        for (int mt = 0; mt < 2; mt++)
#pragma unroll
            for (int nt = 0; nt < 2; nt++)
#pragma unroll
                for (int j = 0; j < 4; j++) acc[g][mt][nt][j] = 0.f;

    auto load_chunk = [&](int c, int s) {
        const uint32_t sb = sbase + s * LF_STAGE;
        const int k0 = c << 6;
#pragma unroll
        for (int i = 0; i < 2; ++i) {
            int p = tid + i * 256;
            int row = p >> 3, cb = p & 7;
            size_t aoff = (size_t)(bm + row) * K + k0 + cb * 8;
            cp16(sb + row * TP144 + cb * 16, Ah + aoff);
        }
#pragma unroll
        for (int i = 0; i < 6; ++i) {
            int p = tid + i * 256;
            int g = p >> 9, pp = p & 511;
            int row = pp >> 3, cb = pp & 7;
            size_t woff = (size_t)(g * 512 + bh + row) * 512 + k0 + cb * 8;
            cp16(sb + LF_AT + g * LF_BT + row * TP144 + cb * 16, g_Wlh + woff);
        }
        CP_COMMIT();
    };

    load_chunk(0, 0);
    load_chunk(1, 1);

    for (int c = 0; c < NC; ++c) {
        if (c + 2 < NC) load_chunk(c + 2, (c + 2) % 3);

        if (c + 2 < NC)      asm volatile("cp.async.wait_group 2;" ::: "memory");
        else if (c + 1 < NC) asm volatile("cp.async.wait_group 1;" ::: "memory");
        else                 asm volatile("cp.async.wait_group 0;" ::: "memory");
        __syncthreads();

        const uint32_t sb = sbase + (c % 3) * LF_STAGE;

#pragma unroll
        for (int ks = 0; ks < 4; ++ks) {
            const int kb = ks * 32;
            uint32_t ah[2][4];
#pragma unroll
            for (int mt = 0; mt < 2; ++mt) {
                uint32_t ro = (wm * 32 + mt * 16 + a_row) * TP144 + a_kb + kb;
                ldsm4(ah[mt], sb + ro);
            }
            uint32_t bg[3][4];
#pragma unroll
            for (int g = 0; g < 3; ++g) {
                uint32_t ro = (wn * 16 + b_row2) * TP144 + b_kb + kb;
                ldsm4(bg[g], sb + LF_AT + g * LF_BT + ro);
            }
#pragma unroll
            for (int g = 0; g < 3; ++g)
#pragma unroll
                for (int mt = 0; mt < 2; ++mt)
#pragma unroll
                    for (int nt = 0; nt < 2; ++nt)
                        mma16816(acc[g][mt][nt], ah[mt], &bg[g][nt * 2]);
        }
        __syncthreads();
    }

    const int r0 = lane >> 2;
    const int q2 = (lane & 3) * 2;
#pragma unroll
    for (int mt = 0; mt < 2; ++mt) {
        // sibling group index for this 16-row block
        int grp = (bm >> 4) + wm * 2 + mt;
#pragma unroll
        for (int nt = 0; nt < 2; ++nt) {
            int col = bh + wn * 16 + nt * 8 + q2;
            float bi0 = g_bleaf[col],        bi1 = g_bleaf[col + 1];
            float bo0 = g_bleaf[512 + col],  bo1 = g_bleaf[512 + col + 1];
            float bu0 = g_bleaf[1024 + col], bu1 = g_bleaf[1024 + col + 1];
            float hs0 = 0.f, hs1 = 0.f;
#pragma unroll
            for (int hf = 0; hf < 2; ++hf) {
                int row = bm + wm * 32 + mt * 16 + r0 + hf * 8;
                float i0 = sigf(acc[0][mt][nt][hf * 2 + 0] + bi0);
                float i1 = sigf(acc[0][mt][nt][hf * 2 + 1] + bi1);
                float o0 = sigf(acc[1][mt][nt][hf * 2 + 0] + bo0);
                float o1 = sigf(acc[1][mt][nt][hf * 2 + 1] + bo1);
                float u0 = tanhf(acc[2][mt][nt][hf * 2 + 0] + bu0);
                float u1 = tanhf(acc[2][mt][nt][hf * 2 + 1] + bu1);
                float c0 = i0 * u0, c1 = i1 * u1;
                hs0 += o0 * tanhf(c0);
                hs1 += o1 * tanhf(c1);
                size_t gci = (size_t)(4369 + row) * HID + col;
                __half2 vc; vc.x = __float2half_rn(c0); vc.y = __float2half_rn(c1);
                *(__half2*)(g_Ch + gci) = vc;
            }
            // reduce over r0 (lane bits 2..4)
#pragma unroll
            for (int m = 4; m <= 16; m <<= 1) {
                hs0 += __shfl_xor_sync(0xffffffffu, hs0, m);
                hs1 += __shfl_xor_sync(0xffffffffu, hs1, m);
            }
            if (r0 == 0) {
                __half2 v; v.x = __float2half_rn(hs0); v.y = __float2half_rn(hs1);
                *(__half2*)(g_XHh + (size_t)grp * 1024 + 512 + col) = v;
            }
        }
    }
}

// ---------------------------------------------------------------------------
// prep: pack weights (blocks [0,8192)) || convert leaf x (blocks [8192,40960))
// ---------------------------------------------------------------------------
__global__ void prep(const float* __restrict__ wi_w, const float* __restrict__ wi_b,
                     const float* __restrict__ wf_w, const float* __restrict__ wf_b,
                     const float* __restrict__ wo_w, const float* __restrict__ wo_b,
                     const float* __restrict__ wu_w, const float* __restrict__ wu_b,
                     const float* __restrict__ xleaf) {
    if (blockIdx.x < 8192) {
        int idx = blockIdx.x * 256 + threadIdx.x;
        if (idx < 2048 * 1024) {
            int r = idx >> 10, k = idx & 1023;
            float v;
            if      (r <  512) v = wi_w[r * 1024 + k];
            else if (r < 1024) v = wo_w[(r -  512) * 1024 + k];
            else if (r < 1536) v = wu_w[(r - 1024) * 1024 + k];
            else               v = (k < 512) ? wf_w[(r - 1536) * 1024 + k] : 0.f;
            g_Wnh[idx] = __float2half_rn(v);
        }
        if (idx < 1536 * 512) {
            int r = idx >> 9, k = idx & 511;
            float v;
            if      (r <  512) v = wi_w[r * 1024 + k];
            else if (r < 1024) v = wo_w[(r -  512) * 1024 + k];
            else               v = wu_w[(r - 1024) * 1024 + k];
            g_Wlh[idx] = __float2half_rn(v);
        }
        if (idx < 512 * 512) {
            int r = idx >> 9, k = idx & 511;
            g_Wfhh[idx] = __float2half_rn(wf_w[r * 1024 + 512 + k]);
        }
        if (idx < 1536)
            g_bleaf[idx] = (idx < 512) ? wi_b[idx]
                         : (idx < 1024) ? wo_b[idx - 512] : wu_b[idx - 1024];
        if (idx < 2048)
            g_bnode[idx] = (idx <  512) ? wi_b[idx]
                         : (idx < 1024) ? wo_b[idx -  512]
                         : (idx < 1536) ? wu_b[idx - 1024] : wf_b[idx - 1536];
    } else {
        int i = (blockIdx.x - 8192) * 256 + threadIdx.x;
        float4 v = ((const float4*)xleaf)[i];
        hlf hh[4];
        hh[0] = __float2half_rn(v.x); hh[1] = __float2half_rn(v.y);
        hh[2] = __float2half_rn(v.z); hh[3] = __float2half_rn(v.w);
        ((uint2*)g_Xh)[i] = *(uint2*)hh;
    }
}

// ---------------------------------------------------------------------------
// Elementwise stages
// ---------------------------------------------------------------------------
// x-part of XH for level 3 (h-part written by leaf_fused)
__global__ void concat_x_l3(const float* __restrict__ x) {
    int idx = blockIdx.x * blockDim.x + threadIdx.x;   // 4096*128
    int r = idx >> 7, c4 = (idx & 127) * 4;
    float4 v = *(const float4*)(x + (size_t)(273 + r) * IN_DIM + c4);
    hlf hh[4];
    hh[0] = __float2half_rn(v.x); hh[1] = __float2half_rn(v.y);
    hh[2] = __float2half_rn(v.z); hh[3] = __float2half_rn(v.w);
    *(uint2*)(g_XHh + (size_t)r * 1024 + c4) = *(uint2*)hh;
}

// full concat for levels d < 3 (children H fp32)
__global__ void concat_xh4(const float* __restrict__ x, int off_d, int off_c, int n) {
    int idx = blockIdx.x * blockDim.x + threadIdx.x;
    if (idx >= n * 256) return;
    int r = idx >> 8, c4 = (idx & 255) * 4;
    float4 v;
    if (c4 < 512) {
        v = *(const float4*)(x + (size_t)(off_d + r) * IN_DIM + c4);
    } else {
        int hc = c4 - 512;
        size_t base = (size_t)(off_c + r * 16) * HID + hc;
        v = make_float4(0.f, 0.f, 0.f, 0.f);
#pragma unroll
        for (int k = 0; k < 16; k++) {
            float4 t = *(const float4*)(g_H + base + k * HID);
            v.x += t.x; v.y += t.y; v.z += t.z; v.w += t.w;
        }
    }
    hlf hh[4];
    hh[0] = __float2half_rn(v.x); hh[1] = __float2half_rn(v.y);
    hh[2] = __float2half_rn(v.z); hh[3] = __float2half_rn(v.w);
    *(uint2*)(g_XHh + (size_t)r * 1024 + c4) = *(uint2*)hh;
}

__global__ void node_epilogue4(int off_d, int off_c, int n, int leafkids) {
    int idx = blockIdx.x * blockDim.x + threadIdx.x;
    if (idx >= n * 128) return;
    int r = idx >> 7, h4 = (idx & 127) * 4;
    const float* g = g_G + (size_t)r * 2048;
    float4 gi = *(const float4*)(g + h4);
    float4 go = *(const float4*)(g + 512 + h4);
    float4 gu = *(const float4*)(g + 1024 + h4);
    float4 gf = *(const float4*)(g + 1536 + h4);
    float a0 = sigf(gi.x) * tanhf(gu.x);
    float a1 = sigf(gi.y) * tanhf(gu.y);
    float a2 = sigf(gi.z) * tanhf(gu.z);
    float a3 = sigf(gi.w) * tanhf(gu.w);
    size_t cb = (size_t)(off_c + r * 16) * HID + h4;
#pragma unroll
    for (int k = 0; k < 16; k++) {
        float4 fh = h4_to_f4(*(const uint2*)(g_FHh + cb + k * HID));
        float4 cc;
        if (leafkids) cc = h4_to_f4(*(const uint2*)(g_Ch + cb + k * HID));
        else          cc = *(const float4*)(g_C + cb + k * HID);
        a0 += sigf(gf.x + fh.x) * cc.x;
        a1 += sigf(gf.y + fh.y) * cc.y;
        a2 += sigf(gf.z + fh.z) * cc.z;
        a3 += sigf(gf.w + fh.w) * cc.w;
    }
    size_t gidx = (size_t)(off_d + r) * HID + h4;
    *(float4*)(g_C + gidx) = make_float4(a0, a1, a2, a3);
    float4 hv = make_float4(sigf(go.x) * tanhf(a0), sigf(go.y) * tanhf(a1),
                            sigf(go.z) * tanhf(a2), sigf(go.w) * tanhf(a3));
    *(float4*)(g_H + gidx) = hv;
    hlf hh[4];
    hh[0] = __float2half_rn(a0); hh[1] = __float2half_rn(a1);
    hh[2] = __float2half_rn(a2); hh[3] = __float2half_rn(a3);
    *(uint2*)(g_Ch + gidx) = *(uint2*)hh;
}

__global__ void writeout(float* __restrict__ out) {
    int idx = blockIdx.x * blockDim.x + threadIdx.x;
    if (idx < 512)       out[idx] = g_H[idx];
    else if (idx < 1024) out[idx] = g_C[idx - 512];
}

// ---------------------------------------------------------------------------
// Launch
// ---------------------------------------------------------------------------
static void launch_gemm(const hlf* Ah, const hlf* Bh, void* Cout,
                        const float* bias, int M, int N, int K, int half_out) {
    if (M >= 1024) {
        dim3 grid(N / 128, (M + 127) / 128);
        gemm_h<<<grid, 256, GSMEM>>>(Ah, Bh, Cout, bias, M, N, K, half_out);
    } else {
        dim3 grid(N / 64, (M + 63) / 64);
        gemm_h64<<<grid, 128, G64_SMEM>>>(Ah, Bh, Cout, bias, M, N, K, half_out);
    }
}

extern "C" void kernel_launch(void* const* d_in, const int* in_sizes, int n_in,
                              void* d_out, int out_size) {
    const float* x    = (const float*)d_in[0];
    const float* wi_w = (const float*)d_in[1];
    const float* wi_b = (const float*)d_in[2];
    const float* wf_w = (const float*)d_in[3];
    const float* wf_b = (const float*)d_in[4];
    const float* wo_w = (const float*)d_in[5];
    const float* wo_b = (const float*)d_in[6];
    const float* wu_w = (const float*)d_in[7];
    const float* wu_b = (const float*)d_in[8];
    float* out = (float*)d_out;

    cudaFuncSetAttribute(gemm_h,     cudaFuncAttributeMaxDynamicSharedMemorySize, GSMEM);
    cudaFuncSetAttribute(gemm_h64,   cudaFuncAttributeMaxDynamicSharedMemorySize, G64_SMEM);
    cudaFuncSetAttribute(leaf_fused, cudaFuncAttributeMaxDynamicSharedMemorySize, LF_SMEM);

    float *pG, *pbn;
    hlf *pXh, *pCh, *pXHh, *pWnh, *pWfhh, *pFHh;
    cudaGetSymbolAddress((void**)&pG,    g_G);
    cudaGetSymbolAddress((void**)&pbn,   g_bnode);
    cudaGetSymbolAddress((void**)&pXh,   g_Xh);
    cudaGetSymbolAddress((void**)&pCh,   g_Ch);
    cudaGetSymbolAddress((void**)&pXHh,  g_XHh);
    cudaGetSymbolAddress((void**)&pWnh,  g_Wnh);
    cudaGetSymbolAddress((void**)&pWfhh, g_Wfhh);
    cudaGetSymbolAddress((void**)&pFHh,  g_FHh);

    static const int offs[6]  = {0, 1, 17, 273, 4369, 69905};
    static const int sizes[5] = {1, 16, 256, 4096, 65536};

    // 1) prep: weights -> fp16 || leaf x -> fp16; x-part of XH level-3
    prep<<<40960, 256>>>(wi_w, wi_b, wf_w, wf_b, wo_w, wo_b, wu_w, wu_b,
                         x + (size_t)offs[4] * IN_DIM);
    concat_x_l3<<<4096 * 128 / 256, 256>>>(x);

    // 2) fused leaf gates (writes Ch + XHh h-part), then FH GEMM (fp16 out)
    {
        dim3 grid(HID / 64, NLEAF / 64);
        leaf_fused<<<grid, 256, LF_SMEM>>>(pXh);
    }
    launch_gemm(pCh + (size_t)offs[4] * HID, pWfhh,
                pFHh + (size_t)offs[4] * HID, nullptr, NLEAF, 512, 512, 1);

    // 3) internal levels, bottom-up
    for (int d = 3; d >= 0; d--) {
        int n = sizes[d];
        int leafkids = (d == 3) ? 1 : 0;
        if (d < 3)
            concat_xh4<<<(n * 256 + 255) / 256, 256>>>(x, offs[d], offs[d + 1], n);
        launch_gemm(pXHh, pWnh, pG, pbn, n, 2048, 1024, 0);
        node_epilogue4<<<(n * 128 + 255) / 256, 256>>>(offs[d], offs[d + 1], n, leafkids);
        if (d > 0)
            launch_gemm(pCh + (size_t)offs[d] * HID, pWfhh,
                        pFHh + (size_t)offs[d] * HID, nullptr, n, 512, 512, 1);
    }

    // 4) output: H[0] then C[0]
    writeout<<<4, 256>>>(out);
}

// round 16
// speedup vs baseline: 1.3495x; 1.0210x over previous
#include <cuda_runtime.h>
#include <cuda_fp16.h>
#include <math.h>
#include <stdint.h>

// ---------------------------------------------------------------------------
// CSTreeLSTM on GB300: single-term fp16 HMMA GEMMs (fp32 accumulate),
// fp16 intermediates everywhere (incl. gate preactivations), BK=64,
// multi-CTA/SM on all GEMMs. leaf_fused folds the sibling H-sum.
// Tree: 16-ary, depth 4, IN=HID=512. Levels 1,16,256,4096,65536
// (offsets 0,1,17,273,4369; total 69905).
// ---------------------------------------------------------------------------

#define IN_DIM 512
#define HID    512
#define NLEAF  65536
#define NTOT   69905

typedef __half hlf;

// ------------------------------ device scratch ------------------------------
__device__ __align__(128) float g_C [NTOT * HID];
__device__ __align__(128) float g_H [NTOT * HID];
__device__ __align__(128) hlf   g_FHh[NTOT * HID];
__device__ __align__(128) hlf   g_Gh [4096 * 2048];   // node gate preacts, fp16

__device__ __align__(128) hlf g_Xh [NLEAF * IN_DIM];
__device__ __align__(128) hlf g_Ch [NTOT * HID];
__device__ __align__(128) hlf g_XHh[4096 * 1024];

__device__ __align__(128) hlf g_Wnh[2048 * 1024];
__device__ __align__(128) hlf g_Wlh[1536 * 512];
__device__ __align__(128) hlf g_Wfhh[512 * 512];
__device__ float g_bleaf[1536];
__device__ float g_bnode[2048];

__device__ __forceinline__ float sigf(float x) { return 1.f / (1.f + expf(-x)); }

// ------------------------------ PTX helpers ---------------------------------
__device__ __forceinline__ uint32_t smem_u32(const void* p) {
    uint32_t a;
    asm("{ .reg .u64 t; cvta.to.shared.u64 t, %1; cvt.u32.u64 %0, t; }" : "=r"(a) : "l"(p));
    return a;
}

__device__ __forceinline__ void cp16(uint32_t dst, const void* src) {
    asm volatile("cp.async.cg.shared.global [%0], [%1], 16;" :: "r"(dst), "l"(src));
}
#define CP_COMMIT() asm volatile("cp.async.commit_group;" ::: "memory")

__device__ __forceinline__ void ldsm4(uint32_t* r, uint32_t addr) {
    asm volatile("ldmatrix.sync.aligned.m8n8.x4.shared.b16 {%0,%1,%2,%3}, [%4];"
                 : "=r"(r[0]), "=r"(r[1]), "=r"(r[2]), "=r"(r[3]) : "r"(addr));
}
__device__ __forceinline__ void mma16816(float* d, const uint32_t* a, const uint32_t* b) {
    asm volatile(
        "mma.sync.aligned.m16n8k16.row.col.f32.f16.f16.f32 "
        "{%0,%1,%2,%3}, {%4,%5,%6,%7}, {%8,%9}, {%0,%1,%2,%3};"
        : "+f"(d[0]), "+f"(d[1]), "+f"(d[2]), "+f"(d[3])
        : "r"(a[0]), "r"(a[1]), "r"(a[2]), "r"(a[3]), "r"(b[0]), "r"(b[1]));
}

__device__ __forceinline__ float4 h4_to_f4(uint2 u) {
    __half2 lo = *(__half2*)&u.x, hi = *(__half2*)&u.y;
    float2 a = __half22float2(lo), b = __half22float2(hi);
    return make_float4(a.x, a.y, b.x, b.y);
}

// ---------------------------------------------------------------------------
// Big GEMM: CTA 128(M) x 128(N), 256 threads / 8 warps, warp tile 32x64,
// BK=64, 3-stage cp.async, 2 CTAs/SM. N%128==0, K%64==0; M guarded.
// ---------------------------------------------------------------------------
#define TP144 144
#define AT_B (128 * TP144)
#define STAGE_B (2 * AT_B)
#define GSMEM (3 * STAGE_B + 128)

__global__ __launch_bounds__(256, 2)
void gemm_h(const hlf* __restrict__ Ah, const hlf* __restrict__ Bh,
            void* __restrict__ Cout, const float* __restrict__ bias,
            int M, int N, int K, int half_out) {
    extern __shared__ char smem_raw[];
    const uint32_t sbase = (smem_u32(smem_raw) + 127) & ~127u;

    const int tid  = threadIdx.x;
    const int lane = tid & 31;
    const int wid  = tid >> 5;
    const int wm   = wid >> 1;
    const int wn   = wid & 1;
    const int bm   = blockIdx.y * 128;
    const int bn   = blockIdx.x * 128;
    const int NC   = K >> 6;

    const int ag = lane >> 3, ai = lane & 7;
    const int a_row = ai + (ag & 1) * 8;
    const int a_kb  = (ag >> 1) * 16;
    const int b_row2 = (lane & 7) + ((lane >> 4) << 3);
    const int b_kb   = ((lane >> 3) & 1) * 16;

    float acc[2][8][4];
#pragma unroll
    for (int mt = 0; mt < 2; mt++)
#pragma unroll
        for (int nt = 0; nt < 8; nt++)
#pragma unroll
            for (int j = 0; j < 4; j++) acc[mt][nt][j] = 0.f;

    auto load_chunk = [&](int c, int s) {
        const uint32_t sb = sbase + s * STAGE_B;
        const int k0 = c << 6;
#pragma unroll
        for (int i = 0; i < 4; ++i) {
            int p = tid + i * 256;
            int row = p >> 3, cb = p & 7;
            int ar = bm + row; if (ar > M - 1) ar = M - 1;
            size_t aoff = (size_t)ar * K + k0 + cb * 8;
            size_t boff = (size_t)(bn + row) * K + k0 + cb * 8;
            uint32_t so = row * TP144 + cb * 16;
            cp16(sb + so,        Ah + aoff);
            cp16(sb + AT_B + so, Bh + boff);
        }
        CP_COMMIT();
    };

    load_chunk(0, 0);
    if (NC > 1) load_chunk(1, 1);

    for (int c = 0; c < NC; ++c) {
        if (c + 2 < NC) load_chunk(c + 2, (c + 2) % 3);

        if (c + 2 < NC)      asm volatile("cp.async.wait_group 2;" ::: "memory");
        else if (c + 1 < NC) asm volatile("cp.async.wait_group 1;" ::: "memory");
        else                 asm volatile("cp.async.wait_group 0;" ::: "memory");
        __syncthreads();

        const uint32_t sb  = sbase + (c % 3) * STAGE_B;
        const uint32_t tAh = sb, tBh = sb + AT_B;

#pragma unroll
        for (int ks = 0; ks < 4; ++ks) {
            const int kb = ks * 32;
            uint32_t ah[2][4], bh[8][2];
#pragma unroll
            for (int mt = 0; mt < 2; ++mt) {
                uint32_t ro = (wm * 32 + mt * 16 + a_row) * TP144 + a_kb + kb;
                ldsm4(ah[mt], tAh + ro);
            }
#pragma unroll
            for (int nt2 = 0; nt2 < 8; nt2 += 2) {
                uint32_t ro = (wn * 64 + nt2 * 8 + b_row2) * TP144 + b_kb + kb;
                ldsm4(&bh[nt2][0], tBh + ro);
            }
#pragma unroll
            for (int mt = 0; mt < 2; ++mt)
#pragma unroll
                for (int nt = 0; nt < 8; ++nt)
                    mma16816(acc[mt][nt], ah[mt], bh[nt]);
        }
        __syncthreads();
    }

    const int r0 = lane >> 2;
    const int q2 = (lane & 3) * 2;
#pragma unroll
    for (int mt = 0; mt < 2; ++mt) {
        int row = bm + wm * 32 + mt * 16 + r0;
#pragma unroll
        for (int nt = 0; nt < 8; ++nt) {
            int col = bn + wn * 64 + nt * 8 + q2;
            float bx = 0.f, by = 0.f;
            if (bias) { bx = bias[col]; by = bias[col + 1]; }
            float v00 = acc[mt][nt][0] + bx, v01 = acc[mt][nt][1] + by;
            float v10 = acc[mt][nt][2] + bx, v11 = acc[mt][nt][3] + by;
            if (half_out) {
                hlf* Ch = (hlf*)Cout;
                if (row < M) {
                    __half2 v; v.x = __float2half_rn(v00); v.y = __float2half_rn(v01);
                    *(__half2*)(Ch + (size_t)row * N + col) = v;
                }
                if (row + 8 < M) {
                    __half2 v; v.x = __float2half_rn(v10); v.y = __float2half_rn(v11);
                    *(__half2*)(Ch + (size_t)(row + 8) * N + col) = v;
                }
            } else {
                float* Cf = (float*)Cout;
                if (row < M)
                    *(float2*)(Cf + (size_t)row * N + col) = make_float2(v00, v01);
                if (row + 8 < M)
                    *(float2*)(Cf + (size_t)(row + 8) * N + col) = make_float2(v10, v11);
            }
        }
    }
}

// ---------------------------------------------------------------------------
// Small GEMM: CTA 64x64, 128 threads / 4 warps (warp tile 32x32), BK=64,
// 3-stage cp.async, 4 CTAs/SM. Used for M < 1024 tails.
// ---------------------------------------------------------------------------
#define G64_T (64 * TP144)              // 9216
#define G64_STAGE (2 * G64_T)           // 18432
#define G64_SMEM (3 * G64_STAGE + 128)  // 55424

__global__ __launch_bounds__(128, 4)
void gemm_h64(const hlf* __restrict__ Ah, const hlf* __restrict__ Bh,
              void* __restrict__ Cout, const float* __restrict__ bias,
              int M, int N, int K, int half_out) {
    extern __shared__ char smem_raw[];
    const uint32_t sbase = (smem_u32(smem_raw) + 127) & ~127u;

    const int tid  = threadIdx.x;
    const int lane = tid & 31;
    const int wid  = tid >> 5;
    const int wm   = wid >> 1;
    const int wn   = wid & 1;
    const int bm   = blockIdx.y * 64;
    const int bn   = blockIdx.x * 64;
    const int NC   = K >> 6;

    const int ag = lane >> 3, ai = lane & 7;
    const int a_row = ai + (ag & 1) * 8;
    const int a_kb  = (ag >> 1) * 16;
    const int b_row2 = (lane & 7) + ((lane >> 4) << 3);
    const int b_kb   = ((lane >> 3) & 1) * 16;

    float acc[2][4][4];
#pragma unroll
    for (int mt = 0; mt < 2; mt++)
#pragma unroll
        for (int nt = 0; nt < 4; nt++)
#pragma unroll
            for (int j = 0; j < 4; j++) acc[mt][nt][j] = 0.f;

    auto load_chunk = [&](int c, int s) {
        const uint32_t sb = sbase + s * G64_STAGE;
        const int k0 = c << 6;
#pragma unroll
        for (int it = 0; it < 4; ++it) {        // 512 positions per tile
            int idx = tid + it * 128;
            int row = idx >> 3, cb = idx & 7;
            int ar = bm + row; if (ar > M - 1) ar = M - 1;
            size_t aoff = (size_t)ar * K + k0 + cb * 8;
            size_t boff = (size_t)(bn + row) * K + k0 + cb * 8;
            uint32_t so = row * TP144 + cb * 16;
            cp16(sb + so,         Ah + aoff);
            cp16(sb + G64_T + so, Bh + boff);
        }
        CP_COMMIT();
    };

    load_chunk(0, 0);
    if (NC > 1) load_chunk(1, 1);

    for (int c = 0; c < NC; ++c) {
        if (c + 2 < NC) load_chunk(c + 2, (c + 2) % 3);

        if (c + 2 < NC)      asm volatile("cp.async.wait_group 2;" ::: "memory");
        else if (c + 1 < NC) asm volatile("cp.async.wait_group 1;" ::: "memory");
        else                 asm volatile("cp.async.wait_group 0;" ::: "memory");
        __syncthreads();

        const uint32_t sb  = sbase + (c % 3) * G64_STAGE;
        const uint32_t tAh = sb, tBh = sb + G64_T;

#pragma unroll
        for (int ks = 0; ks < 4; ++ks) {
            const int kb = ks * 32;
            uint32_t ah[2][4], bh[4][2];
#pragma unroll
            for (int mt = 0; mt < 2; ++mt) {
                uint32_t ro = (wm * 32 + mt * 16 + a_row) * TP144 + a_kb + kb;
                ldsm4(ah[mt], tAh + ro);
            }
#pragma unroll
            for (int nt2 = 0; nt2 < 4; nt2 += 2) {
                uint32_t ro = (wn * 32 + nt2 * 8 + b_row2) * TP144 + b_kb + kb;
                ldsm4(&bh[nt2][0], tBh + ro);
            }
#pragma unroll
            for (int mt = 0; mt < 2; ++mt)
#pragma unroll
                for (int nt = 0; nt < 4; ++nt)
                    mma16816(acc[mt][nt], ah[mt], bh[nt]);
        }
        __syncthreads();
    }

    const int r0 = lane >> 2;
    const int q2 = (lane & 3) * 2;
#pragma unroll
    for (int mt = 0; mt < 2; ++mt) {
        int row = bm + wm * 32 + mt * 16 + r0;
#pragma unroll
        for (int nt = 0; nt < 4; ++nt) {
            int col = bn + wn * 32 + nt * 8 + q2;
            float bx = 0.f, by = 0.f;
            if (bias) { bx = bias[col]; by = bias[col + 1]; }
            float v00 = acc[mt][nt][0] + bx, v01 = acc[mt][nt][1] + by;
            float v10 = acc[mt][nt][2] + bx, v11 = acc[mt][nt][3] + by;
            if (half_out) {
                hlf* Ch = (hlf*)Cout;
                if (row < M) {
                    __half2 v; v.x = __float2half_rn(v00); v.y = __float2half_rn(v01);
                    *(__half2*)(Ch + (size_t)row * N + col) = v;
                }
                if (row + 8 < M) {
                    __half2 v; v.x = __float2half_rn(v10); v.y = __float2half_rn(v11);
                    *(__half2*)(Ch + (size_t)(row + 8) * N + col) = v;
                }
            } else {
                float* Cf = (float*)Cout;
                if (row < M)
                    *(float2*)(Cf + (size_t)row * N + col) = make_float2(v00, v01);
                if (row + 8 < M)
                    *(float2*)(Cf + (size_t)(row + 8) * N + col) = make_float2(v10, v11);
            }
        }
    }
}

// ---------------------------------------------------------------------------
// Fused leaf kernel. CTA 64(M) x 64(h) x 3 gates, 256 threads / 8 warps,
// warp layout 2(M)x4(h), warp tile 32x16/gate, BK=64, 3 stages, 2 CTAs/SM.
// Epilogue: Ch (fp16) + 16-way sibling h-sum into XHh[grp][512+col].
// ---------------------------------------------------------------------------
#define LF_AT (64 * TP144)
#define LF_BT (64 * TP144)
#define LF_STAGE (LF_AT + 3 * LF_BT)
#define LF_SMEM (3 * LF_STAGE + 128)

__global__ __launch_bounds__(256, 2)
void leaf_fused(const hlf* __restrict__ Ah) {
    extern __shared__ char smem_raw[];
    const uint32_t sbase = (smem_u32(smem_raw) + 127) & ~127u;

    const int tid  = threadIdx.x;
    const int lane = tid & 31;
    const int wid  = tid >> 5;
    const int wm   = wid >> 2;
    const int wn   = wid & 3;
    const int bm   = blockIdx.y * 64;
    const int bh   = blockIdx.x * 64;
    const int K    = 512;
    const int NC   = 8;

    const int ag = lane >> 3, ai = lane & 7;
    const int a_row = ai + (ag & 1) * 8;
    const int a_kb  = (ag >> 1) * 16;
    const int b_row2 = (lane & 7) + ((lane >> 4) << 3);
    const int b_kb   = ((lane >> 3) & 1) * 16;

    float acc[3][2][2][4];
#pragma unroll
    for (int g = 0; g < 3; g++)
#pragma unroll
        for (int mt = 0; mt < 2; mt++)
#pragma unroll
            for (int nt = 0; nt < 2; nt++)
#pragma unroll
                for (int j = 0; j < 4; j++) acc[g][mt][nt][j] = 0.f;

    auto load_chunk = [&](int c, int s) {
        const uint32_t sb = sbase + s * LF_STAGE;
        const int k0 = c << 6;
#pragma unroll
        for (int i = 0; i < 2; ++i) {
            int p = tid + i * 256;
            int row = p >> 3, cb = p & 7;
            size_t aoff = (size_t)(bm + row) * K + k0 + cb * 8;
            cp16(sb + row * TP144 + cb * 16, Ah + aoff);
        }
#pragma unroll
        for (int i = 0; i < 6; ++i) {
            int p = tid + i * 256;
            int g = p >> 9, pp = p & 511;
            int row = pp >> 3, cb = pp & 7;
            size_t woff = (size_t)(g * 512 + bh + row) * 512 + k0 + cb * 8;
            cp16(sb + LF_AT + g * LF_BT + row * TP144 + cb * 16, g_Wlh + woff);
        }
        CP_COMMIT();
    };

    load_chunk(0, 0);
    load_chunk(1, 1);

    for (int c = 0; c < NC; ++c) {
        if (c + 2 < NC) load_chunk(c + 2, (c + 2) % 3);

        if (c + 2 < NC)      asm volatile("cp.async.wait_group 2;" ::: "memory");
        else if (c + 1 < NC) asm volatile("cp.async.wait_group 1;" ::: "memory");
        else                 asm volatile("cp.async.wait_group 0;" ::: "memory");
        __syncthreads();

        const uint32_t sb = sbase + (c % 3) * LF_STAGE;

#pragma unroll
        for (int ks = 0; ks < 4; ++ks) {
            const int kb = ks * 32;
            uint32_t ah[2][4];
#pragma unroll
            for (int mt = 0; mt < 2; ++mt) {
                uint32_t ro = (wm * 32 + mt * 16 + a_row) * TP144 + a_kb + kb;
                ldsm4(ah[mt], sb + ro);
            }
            uint32_t bg[3][4];
#pragma unroll
            for (int g = 0; g < 3; ++g) {
                uint32_t ro = (wn * 16 + b_row2) * TP144 + b_kb + kb;
                ldsm4(bg[g], sb + LF_AT + g * LF_BT + ro);
            }
#pragma unroll
            for (int g = 0; g < 3; ++g)
#pragma unroll
                for (int mt = 0; mt < 2; ++mt)
#pragma unroll
                    for (int nt = 0; nt < 2; ++nt)
                        mma16816(acc[g][mt][nt], ah[mt], &bg[g][nt * 2]);
        }
        __syncthreads();
    }

    const int r0 = lane >> 2;
    const int q2 = (lane & 3) * 2;
#pragma unroll
    for (int mt = 0; mt < 2; ++mt) {
        int grp = (bm >> 4) + wm * 2 + mt;
#pragma unroll
        for (int nt = 0; nt < 2; ++nt) {
            int col = bh + wn * 16 + nt * 8 + q2;
            float bi0 = g_bleaf[col],        bi1 = g_bleaf[col + 1];
            float bo0 = g_bleaf[512 + col],  bo1 = g_bleaf[512 + col + 1];
            float bu0 = g_bleaf[1024 + col], bu1 = g_bleaf[1024 + col + 1];
            float hs0 = 0.f, hs1 = 0.f;
#pragma unroll
            for (int hf = 0; hf < 2; ++hf) {
                int row = bm + wm * 32 + mt * 16 + r0 + hf * 8;
                float i0 = sigf(acc[0][mt][nt][hf * 2 + 0] + bi0);
                float i1 = sigf(acc[0][mt][nt][hf * 2 + 1] + bi1);
                float o0 = sigf(acc[1][mt][nt][hf * 2 + 0] + bo0);
                float o1 = sigf(acc[1][mt][nt][hf * 2 + 1] + bo1);
                float u0 = tanhf(acc[2][mt][nt][hf * 2 + 0] + bu0);
                float u1 = tanhf(acc[2][mt][nt][hf * 2 + 1] + bu1);
                float c0 = i0 * u0, c1 = i1 * u1;
                hs0 += o0 * tanhf(c0);
                hs1 += o1 * tanhf(c1);
                size_t gci = (size_t)(4369 + row) * HID + col;
                __half2 vc; vc.x = __float2half_rn(c0); vc.y = __float2half_rn(c1);
                *(__half2*)(g_Ch + gci) = vc;
            }
#pragma unroll
            for (int m = 4; m <= 16; m <<= 1) {
                hs0 += __shfl_xor_sync(0xffffffffu, hs0, m);
                hs1 += __shfl_xor_sync(0xffffffffu, hs1, m);
            }
            if (r0 == 0) {
                __half2 v; v.x = __float2half_rn(hs0); v.y = __float2half_rn(hs1);
                *(__half2*)(g_XHh + (size_t)grp * 1024 + 512 + col) = v;
            }
        }
    }
}

// ---------------------------------------------------------------------------
// prep: pack weights (blocks [0,8192)) || convert leaf x (blocks [8192,40960))
// ---------------------------------------------------------------------------
__global__ void prep(const float* __restrict__ wi_w, const float* __restrict__ wi_b,
                     const float* __restrict__ wf_w, const float* __restrict__ wf_b,
                     const float* __restrict__ wo_w, const float* __restrict__ wo_b,
                     const float* __restrict__ wu_w, const float* __restrict__ wu_b,
                     const float* __restrict__ xleaf) {
    if (blockIdx.x < 8192) {
        int idx = blockIdx.x * 256 + threadIdx.x;
        if (idx < 2048 * 1024) {
            int r = idx >> 10, k = idx & 1023;
            float v;
            if      (r <  512) v = wi_w[r * 1024 + k];
            else if (r < 1024) v = wo_w[(r -  512) * 1024 + k];
            else if (r < 1536) v = wu_w[(r - 1024) * 1024 + k];
            else               v = (k < 512) ? wf_w[(r - 1536) * 1024 + k] : 0.f;
            g_Wnh[idx] = __float2half_rn(v);
        }
        if (idx < 1536 * 512) {
            int r = idx >> 9, k = idx & 511;
            float v;
            if      (r <  512) v = wi_w[r * 1024 + k];
            else if (r < 1024) v = wo_w[(r -  512) * 1024 + k];
            else               v = wu_w[(r - 1024) * 1024 + k];
            g_Wlh[idx] = __float2half_rn(v);
        }
        if (idx < 512 * 512) {
            int r = idx >> 9, k = idx & 511;
            g_Wfhh[idx] = __float2half_rn(wf_w[r * 1024 + 512 + k]);
        }
        if (idx < 1536)
            g_bleaf[idx] = (idx < 512) ? wi_b[idx]
                         : (idx < 1024) ? wo_b[idx - 512] : wu_b[idx - 1024];
        if (idx < 2048)
            g_bnode[idx] = (idx <  512) ? wi_b[idx]
                         : (idx < 1024) ? wo_b[idx -  512]
                         : (idx < 1536) ? wu_b[idx - 1024] : wf_b[idx - 1536];
    } else {
        int i = (blockIdx.x - 8192) * 256 + threadIdx.x;
        float4 v = ((const float4*)xleaf)[i];
        hlf hh[4];
        hh[0] = __float2half_rn(v.x); hh[1] = __float2half_rn(v.y);
        hh[2] = __float2half_rn(v.z); hh[3] = __float2half_rn(v.w);
        ((uint2*)g_Xh)[i] = *(uint2*)hh;
    }
}

// ---------------------------------------------------------------------------
// Elementwise stages
// ---------------------------------------------------------------------------
__global__ void concat_x_l3(const float* __restrict__ x) {
    int idx = blockIdx.x * blockDim.x + threadIdx.x;
    int r = idx >> 7, c4 = (idx & 127) * 4;
    float4 v = *(const float4*)(x + (size_t)(273 + r) * IN_DIM + c4);
    hlf hh[4];
    hh[0] = __float2half_rn(v.x); hh[1] = __float2half_rn(v.y);
    hh[2] = __float2half_rn(v.z); hh[3] = __float2half_rn(v.w);
    *(uint2*)(g_XHh + (size_t)r * 1024 + c4) = *(uint2*)hh;
}

__global__ void concat_xh4(const float* __restrict__ x, int off_d, int off_c, int n) {
    int idx = blockIdx.x * blockDim.x + threadIdx.x;
    if (idx >= n * 256) return;
    int r = idx >> 8, c4 = (idx & 255) * 4;
    float4 v;
    if (c4 < 512) {
        v = *(const float4*)(x + (size_t)(off_d + r) * IN_DIM + c4);
    } else {
        int hc = c4 - 512;
        size_t base = (size_t)(off_c + r * 16) * HID + hc;
        v = make_float4(0.f, 0.f, 0.f, 0.f);
#pragma unroll
        for (int k = 0; k < 16; k++) {
            float4 t = *(const float4*)(g_H + base + k * HID);
            v.x += t.x; v.y += t.y; v.z += t.z; v.w += t.w;
        }
    }
    hlf hh[4];
    hh[0] = __float2half_rn(v.x); hh[1] = __float2half_rn(v.y);
    hh[2] = __float2half_rn(v.z); hh[3] = __float2half_rn(v.w);
    *(uint2*)(g_XHh + (size_t)r * 1024 + c4) = *(uint2*)hh;
}

__global__ void node_epilogue4(int off_d, int off_c, int n, int leafkids) {
    int idx = blockIdx.x * blockDim.x + threadIdx.x;
    if (idx >= n * 128) return;
    int r = idx >> 7, h4 = (idx & 127) * 4;
    const hlf* g = g_Gh + (size_t)r * 2048;
    float4 gi = h4_to_f4(*(const uint2*)(g + h4));
    float4 go = h4_to_f4(*(const uint2*)(g + 512 + h4));
    float4 gu = h4_to_f4(*(const uint2*)(g + 1024 + h4));
    float4 gf = h4_to_f4(*(const uint2*)(g + 1536 + h4));
    float a0 = sigf(gi.x) * tanhf(gu.x);
    float a1 = sigf(gi.y) * tanhf(gu.y);
    float a2 = sigf(gi.z) * tanhf(gu.z);
    float a3 = sigf(gi.w) * tanhf(gu.w);
    size_t cb = (size_t)(off_c + r * 16) * HID + h4;
#pragma unroll
    for (int k = 0; k < 16; k++) {
        float4 fh = h4_to_f4(*(const uint2*)(g_FHh + cb + k * HID));
        float4 cc;
        if (leafkids) cc = h4_to_f4(*(const uint2*)(g_Ch + cb + k * HID));
        else          cc = *(const float4*)(g_C + cb + k * HID);
        a0 += sigf(gf.x + fh.x) * cc.x;
        a1 += sigf(gf.y + fh.y) * cc.y;
        a2 += sigf(gf.z + fh.z) * cc.z;
        a3 += sigf(gf.w + fh.w) * cc.w;
    }
    size_t gidx = (size_t)(off_d + r) * HID + h4;
    *(float4*)(g_C + gidx) = make_float4(a0, a1, a2, a3);
    float4 hv = make_float4(sigf(go.x) * tanhf(a0), sigf(go.y) * tanhf(a1),
                            sigf(go.z) * tanhf(a2), sigf(go.w) * tanhf(a3));
    *(float4*)(g_H + gidx) = hv;
    hlf hh[4];
    hh[0] = __float2half_rn(a0); hh[1] = __float2half_rn(a1);
    hh[2] = __float2half_rn(a2); hh[3] = __float2half_rn(a3);
    *(uint2*)(g_Ch + gidx) = *(uint2*)hh;
}

__global__ void writeout(float* __restrict__ out) {
    int idx = blockIdx.x * blockDim.x + threadIdx.x;
    if (idx < 512)       out[idx] = g_H[idx];
    else if (idx < 1024) out[idx] = g_C[idx - 512];
}

// ---------------------------------------------------------------------------
// Launch
// ---------------------------------------------------------------------------
static void launch_gemm(const hlf* Ah, const hlf* Bh, void* Cout,
                        const float* bias, int M, int N, int K, int half_out) {
    if (M >= 1024) {
        dim3 grid(N / 128, (M + 127) / 128);
        gemm_h<<<grid, 256, GSMEM>>>(Ah, Bh, Cout, bias, M, N, K, half_out);
    } else {
        dim3 grid(N / 64, (M + 63) / 64);
        gemm_h64<<<grid, 128, G64_SMEM>>>(Ah, Bh, Cout, bias, M, N, K, half_out);
    }
}

extern "C" void kernel_launch(void* const* d_in, const int* in_sizes, int n_in,
                              void* d_out, int out_size) {
    const float* x    = (const float*)d_in[0];
    const float* wi_w = (const float*)d_in[1];
    const float* wi_b = (const float*)d_in[2];
    const float* wf_w = (const float*)d_in[3];
    const float* wf_b = (const float*)d_in[4];
    const float* wo_w = (const float*)d_in[5];
    const float* wo_b = (const float*)d_in[6];
    const float* wu_w = (const float*)d_in[7];
    const float* wu_b = (const float*)d_in[8];
    float* out = (float*)d_out;

    cudaFuncSetAttribute(gemm_h,     cudaFuncAttributeMaxDynamicSharedMemorySize, GSMEM);
    cudaFuncSetAttribute(gemm_h64,   cudaFuncAttributeMaxDynamicSharedMemorySize, G64_SMEM);
    cudaFuncSetAttribute(leaf_fused, cudaFuncAttributeMaxDynamicSharedMemorySize, LF_SMEM);

    float *pbn;
    hlf *pXh, *pCh, *pXHh, *pWnh, *pWfhh, *pFHh, *pGh;
    cudaGetSymbolAddress((void**)&pbn,   g_bnode);
    cudaGetSymbolAddress((void**)&pXh,   g_Xh);
    cudaGetSymbolAddress((void**)&pCh,   g_Ch);
    cudaGetSymbolAddress((void**)&pXHh,  g_XHh);
    cudaGetSymbolAddress((void**)&pWnh,  g_Wnh);
    cudaGetSymbolAddress((void**)&pWfhh, g_Wfhh);
    cudaGetSymbolAddress((void**)&pFHh,  g_FHh);
    cudaGetSymbolAddress((void**)&pGh,   g_Gh);

    static const int offs[6]  = {0, 1, 17, 273, 4369, 69905};
    static const int sizes[5] = {1, 16, 256, 4096, 65536};

    // 1) prep: weights -> fp16 || leaf x -> fp16; x-part of XH level-3
    prep<<<40960, 256>>>(wi_w, wi_b, wf_w, wf_b, wo_w, wo_b, wu_w, wu_b,
                         x + (size_t)offs[4] * IN_DIM);
    concat_x_l3<<<4096 * 128 / 256, 256>>>(x);

    // 2) fused leaf gates (writes Ch + XHh h-part), then FH GEMM (fp16 out)
    {
        dim3 grid(HID / 64, NLEAF / 64);
        leaf_fused<<<grid, 256, LF_SMEM>>>(pXh);
    }
    launch_gemm(pCh + (size_t)offs[4] * HID, pWfhh,
                pFHh + (size_t)offs[4] * HID, nullptr, NLEAF, 512, 512, 1);

    // 3) internal levels, bottom-up
    for (int d = 3; d >= 0; d--) {
        int n = sizes[d];
        int leafkids = (d == 3) ? 1 : 0;
        if (d < 3)
            concat_xh4<<<(n * 256 + 255) / 256, 256>>>(x, offs[d], offs[d + 1], n);
        launch_gemm(pXHh, pWnh, pGh, pbn, n, 2048, 1024, 1);
        node_epilogue4<<<(n * 128 + 255) / 256, 256>>>(offs[d], offs[d + 1], n, leafkids);
        if (d > 0)
            launch_gemm(pCh + (size_t)offs[d] * HID, pWfhh,
                        pFHh + (size_t)offs[d] * HID, nullptr, n, 512, 512, 1);
    }

    // 4) output: H[0] then C[0]
    writeout<<<4, 256>>>(out);
}